// round 3
// baseline (speedup 1.0000x reference)
#include <cuda_runtime.h>
#include <math.h>

#define RESX   128
#define NVOX   (RESX*RESX*RESX)
#define NRAYS  1024
#define NS     891

#define ACT_SHIFT (-4.5951198501345898f)   // log(1/(1-0.01)-1)

// ---------------- global scratch (device globals: allowed) ----------------
__device__ float g_norm[3*NVOX];          // normalized sobel normals
__device__ float g_w[NRAYS*NS];           // per-sample weights (in-box range only)
__device__ float g_T[NRAYS];              // final transmittance
__device__ float g_tmin[NRAYS];
__device__ float g_invn[NRAYS];
__device__ int   g_sstart[NRAYS];
__device__ int   g_scnt[NRAYS];
__device__ int   g_base[NRAYS+1];         // exclusive prefix of scnt
__device__ int   g_total;
__device__ float g_c0[NRAYS*NS];
__device__ float g_c1[NRAYS*NS];
__device__ float g_c2[NRAYS*NS];

// ---------------------------------------------------------------------------
// Kernel 1: 5x5x5 conv of density with sobel kernel, zero pad 2, normalize.
// ---------------------------------------------------------------------------
__global__ void __launch_bounds__(256) conv_kernel(const float* __restrict__ dens,
                                                   const float* __restrict__ kern)
{
    __shared__ float sk[375];
    __shared__ float tile[8*12*36];

    int tc = threadIdx.x;          // 0..31 (c fastest)
    int tb = threadIdx.y;          // 0..7
    int tid = tb*32 + tc;
    int c0 = blockIdx.x*32;
    int b0 = blockIdx.y*8;
    int a0 = blockIdx.z*4;

    for (int i=tid; i<375; i+=256) sk[i] = kern[i];
    for (int i=tid; i<8*12*36; i+=256){
        int ic = i % 36; int r = i / 36; int ib = r % 12; int ia = r / 12;
        int ga = a0 - 2 + ia, gb = b0 - 2 + ib, gc = c0 - 2 + ic;
        float v = 0.f;
        if ((unsigned)ga < 128u && (unsigned)gb < 128u && (unsigned)gc < 128u)
            v = dens[(ga*128 + gb)*128 + gc];
        tile[i] = v;
    }
    __syncthreads();

    float s0[4] = {0,0,0,0}, s1[4] = {0,0,0,0}, s2[4] = {0,0,0,0};
    for (int db=0; db<5; db++){
        for (int dc=0; dc<5; dc++){
            float tv[8];
            #pragma unroll
            for (int ia=0; ia<8; ia++)
                tv[ia] = tile[(ia*12 + tb + db)*36 + tc + dc];
            #pragma unroll
            for (int da=0; da<5; da++){
                float k0 = sk[0*125 + da*25 + db*5 + dc];
                float k1 = sk[1*125 + da*25 + db*5 + dc];
                float k2 = sk[2*125 + da*25 + db*5 + dc];
                #pragma unroll
                for (int v=0; v<4; v++){
                    float x = tv[v+da];
                    s0[v] = fmaf(k0, x, s0[v]);
                    s1[v] = fmaf(k1, x, s1[v]);
                    s2[v] = fmaf(k2, x, s2[v]);
                }
            }
        }
    }
    #pragma unroll
    for (int v=0; v<4; v++){
        int idx = ((a0+v)*128 + (b0+tb))*128 + (c0+tc);
        float n0 = s0[v], n1 = s1[v], n2 = s2[v];
        float len = sqrtf(n0*n0 + n1*n1 + n2*n2);
        float inv = -1.f / fmaxf(len, 1e-12f);
        g_norm[idx]          = n0*inv;
        g_norm[NVOX + idx]   = n1*inv;
        g_norm[2*NVOX + idx] = n2*inv;
    }
}

// ---------------------------------------------------------------------------
// packed fp32x2 helpers
// ---------------------------------------------------------------------------
typedef unsigned long long u64;
__device__ __forceinline__ u64 f2pack(float lo, float hi){
    u64 r; asm("mov.b64 %0,{%1,%2};" : "=l"(r) : "f"(lo), "f"(hi)); return r;
}
__device__ __forceinline__ void f2unpack(u64 v, float& lo, float& hi){
    asm("mov.b64 {%0,%1},%2;" : "=f"(lo), "=f"(hi) : "l"(v));
}
__device__ __forceinline__ u64 ffma2(u64 a, u64 b, u64 c){
    u64 d; asm("fma.rn.f32x2 %0,%1,%2,%3;" : "=l"(d) : "l"(a), "l"(b), "l"(c)); return d;
}
// h[32] += v * row[0..63], weights fetched as 16B vectors
__device__ __forceinline__ void accum_row(u64* h, float v, const float* row){
    u64 vv = f2pack(v, v);
    const ulonglong2* wr = (const ulonglong2*)row;
    #pragma unroll
    for (int k=0; k<16; k++){
        ulonglong2 w2 = wr[k];
        h[2*k]   = ffma2(vv, w2.x, h[2*k]);
        h[2*k+1] = ffma2(vv, w2.y, h[2*k+1]);
    }
}

__device__ __forceinline__ void tri_setup(float px, float py, float pz,
                                          int* off, float* w)
{
    float ga = (px + 1.f)*0.5f*127.f;
    float gb = (py + 1.f)*0.5f*127.f;
    float gc = (pz + 1.f)*0.5f*127.f;
    float fa0 = floorf(ga), fb0 = floorf(gb), fc0 = floorf(gc);
    float fa = ga - fa0, fb = gb - fb0, fc = gc - fc0;
    int a0 = min(max((int)fa0, 0), 127);
    int b0 = min(max((int)fb0, 0), 127);
    int c0 = min(max((int)fc0, 0), 127);
    int a1 = min(a0+1, 127), b1 = min(b0+1, 127), c1 = min(c0+1, 127);
    int A0 = a0*16384, A1 = a1*16384, B0 = b0*128, B1 = b1*128;
    off[0]=A0+B0+c0; off[1]=A0+B0+c1; off[2]=A0+B1+c0; off[3]=A0+B1+c1;
    off[4]=A1+B0+c0; off[5]=A1+B0+c1; off[6]=A1+B1+c0; off[7]=A1+B1+c1;
    float wa0 = 1.f-fa, wb0 = 1.f-fb, wc0 = 1.f-fc;
    w[0]=wa0*wb0*wc0; w[1]=wa0*wb0*fc; w[2]=wa0*fb*wc0; w[3]=wa0*fb*fc;
    w[4]=fa*wb0*wc0;  w[5]=fa*wb0*fc;  w[6]=fa*fb*wc0;  w[7]=fa*fb*fc;
}

// ---------------------------------------------------------------------------
// Kernel 2: per-ray prep. alpha per sample, transmittance scan, in-box
// interval + weights to global.
// ---------------------------------------------------------------------------
__global__ void __launch_bounds__(128) prep_kernel(
    const float* __restrict__ ro, const float* __restrict__ rdv,
    const float* __restrict__ grid)
{
    __shared__ float aw[NS];
    __shared__ int s_min, s_max;
    int tid = threadIdx.x;
    int rid = blockIdx.x;
    if (tid == 0){ s_min = 0x7fffffff; s_max = -1; }
    __syncthreads();

    float ox = ro[rid*3+0], oy = ro[rid*3+1], oz = ro[rid*3+2];
    float dx = rdv[rid*3+0], dy = rdv[rid*3+1], dz = rdv[rid*3+2];

    float vecx = (dx == 0.f) ? 1e-6f : dx;
    float vecy = (dy == 0.f) ? 1e-6f : dy;
    float vecz = (dz == 0.f) ? 1e-6f : dz;
    float rax = ( 1.f - ox)/vecx, rbx = (-1.f - ox)/vecx;
    float ray_ = ( 1.f - oy)/vecy, rby = (-1.f - oy)/vecy;
    float raz = ( 1.f - oz)/vecz, rbz = (-1.f - oz)/vecz;
    float tmin = fmaxf(fmaxf(fminf(rax,rbx), fminf(ray_,rby)), fminf(raz,rbz));
    tmin = fminf(fmaxf(tmin, 0.2f), 3.0f);
    float tmax = fminf(fminf(fmaxf(rax,rbx), fmaxf(ray_,rby)), fmaxf(raz,rbz));
    tmax = fminf(fmaxf(tmax, 0.2f), 3.0f);
    bool maskray = (tmax <= tmin);
    float invn = 1.f / sqrtf(dx*dx + dy*dy + dz*dz);

    int lmin = 0x7fffffff, lmax = -1;
    for (int s=tid; s<NS; s+=128){
        float t  = tmin + (0.0078125f * (float)s) * invn;
        float px = fmaf(dx, t, ox), py = fmaf(dy, t, oy), pz = fmaf(dz, t, oz);
        bool in = (!maskray) &&
                  !(px < -1.f || px > 1.f || py < -1.f || py > 1.f || pz < -1.f || pz > 1.f);
        float a = 0.f;
        if (in){
            int off[8]; float wc[8];
            tri_setup(px, py, pz, off, wc);
            float l0 = 0.f;
            #pragma unroll
            for (int k=0; k<8; k++) l0 = fmaf(wc[k], __ldg(grid + off[k]), l0);
            float xs = l0 + ACT_SHIFT;
            float sp = fmaxf(xs, 0.f) + log1pf(expf(-fabsf(xs)));
            a = 1.f - expf(-sp*0.5f);
            lmin = min(lmin, s); lmax = max(lmax, s);
        }
        aw[s] = a;
    }
    if (lmax >= 0){ atomicMin(&s_min, lmin); atomicMax(&s_max, lmax); }
    __syncthreads();

    if (tid == 0){
        float T = 1.f;
        for (int s=0; s<NS; s++){
            float a = aw[s];
            aw[s] = a * T;
            T *= fmaxf(1.f - a, 1e-10f);
        }
        g_T[rid]    = T;
        g_tmin[rid] = tmin;
        g_invn[rid] = invn;
        int cnt = (s_max >= s_min) ? (s_max - s_min + 1) : 0;
        g_sstart[rid] = (cnt > 0) ? s_min : 0;
        g_scnt[rid]   = cnt;
    }
    __syncthreads();

    int smn = s_min, smx = s_max;
    if (smx >= smn){
        for (int s=smn+tid; s<=smx; s+=128)
            g_w[rid*NS + s] = aw[s];
    }
}

// ---------------------------------------------------------------------------
// Kernel 3: exclusive prefix sum over 1024 ray counts.
// ---------------------------------------------------------------------------
__global__ void __launch_bounds__(1024) scan_kernel()
{
    __shared__ int tmp[NRAYS];
    int t = threadIdx.x;
    tmp[t] = g_scnt[t];
    __syncthreads();
    for (int o=1; o<NRAYS; o<<=1){
        int a = (t >= o) ? tmp[t-o] : 0;
        __syncthreads();
        tmp[t] += a;
        __syncthreads();
    }
    g_base[t+1] = tmp[t];
    if (t == 0) g_base[0] = 0;
    if (t == NRAYS-1) g_total = tmp[t];
}

// ---------------------------------------------------------------------------
// Kernel 4: balanced MLP over dense entry list. No shared staging: the
// activation vector lives in a per-thread LOCAL array (L1-backed), the
// packed f32x2 accumulators ping-pong through a single register set, so
// smem = weights only (52 KB) and regs <= 128 -> 4 blocks/SM, 16 warps.
// ---------------------------------------------------------------------------
#define OFF_W0   0
#define OFF_B0   3456
#define OFF_W1   3520
#define OFF_B1   7616
#define OFF_W2   7680
#define OFF_B2   11776
#define OFF_W3   11840
#define OFF_B3   12032
#define OFF_BASE 12036
#define SH_FLOATS 13064
#define SMEM_MLP (SH_FLOATS*4)
#define MLP_BLOCKS 592
#define MLP_NTH 128

__global__ void __launch_bounds__(MLP_NTH, 4) mlp_kernel(
    const float* __restrict__ ro,  const float* __restrict__ rdv,
    const float* __restrict__ vdv, const float* __restrict__ grid,
    const float* __restrict__ w0,  const float* __restrict__ b0,
    const float* __restrict__ w1,  const float* __restrict__ b1,
    const float* __restrict__ w2,  const float* __restrict__ b2,
    const float* __restrict__ w3,  const float* __restrict__ b3)
{
    extern __shared__ float sh[];
    int tid = threadIdx.x;
    int* sbase = (int*)(sh + OFF_BASE);

    for (int i=tid; i<3456; i+=MLP_NTH) sh[OFF_W0+i] = w0[i];
    for (int i=tid; i<64;   i+=MLP_NTH) sh[OFF_B0+i] = b0[i];
    for (int i=tid; i<4096; i+=MLP_NTH) sh[OFF_W1+i] = w1[i];
    for (int i=tid; i<64;   i+=MLP_NTH) sh[OFF_B1+i] = b1[i];
    for (int i=tid; i<4096; i+=MLP_NTH) sh[OFF_W2+i] = w2[i];
    for (int i=tid; i<64;   i+=MLP_NTH) sh[OFF_B2+i] = b2[i];
    for (int i=tid; i<192;  i+=MLP_NTH) sh[OFF_W3+i] = w3[i];
    if (tid < 3) sh[OFF_B3+tid] = b3[tid];
    for (int i=tid; i<NRAYS+1; i+=MLP_NTH) sbase[i] = g_base[i];
    __syncthreads();

    int total = g_total;
    float stage[64];   // runtime-indexed -> local memory (L1), coalesced

    for (int e = blockIdx.x*MLP_NTH + tid; e < total; e += MLP_BLOCKS*MLP_NTH){
        // binary search: largest ray with sbase[ray] <= e
        int lo = 0, hi = NRAYS;
        while (hi - lo > 1){
            int mid = (lo + hi) >> 1;
            if (sbase[mid] <= e) lo = mid; else hi = mid;
        }
        int ray = lo;
        int s = g_sstart[ray] + (e - sbase[ray]);

        float ox = __ldg(ro+ray*3+0), oy = __ldg(ro+ray*3+1), oz = __ldg(ro+ray*3+2);
        float dx = __ldg(rdv+ray*3+0), dy = __ldg(rdv+ray*3+1), dz = __ldg(rdv+ray*3+2);
        float vx = __ldg(vdv+ray*3+0), vy = __ldg(vdv+ray*3+1), vz = __ldg(vdv+ray*3+2);
        float tmin = __ldg(&g_tmin[ray]);
        float invn = __ldg(&g_invn[ray]);
        float wgt  = __ldg(&g_w[ray*NS + s]);

        float t  = tmin + (0.0078125f * (float)s) * invn;
        float px = fmaf(dx, t, ox), py = fmaf(dy, t, oy), pz = fmaf(dz, t, oz);

        int off[8]; float wc[8];
        tri_setup(px, py, pz, off, wc);

        // normals trilinear (consumed immediately; only 3 floats stay live)
        float nsx = 0.f, nsy = 0.f, nsz = 0.f;
        #pragma unroll
        for (int k=0; k<8; k++){
            nsx = fmaf(wc[k], __ldg(g_norm + off[k]),          nsx);
            nsy = fmaf(wc[k], __ldg(g_norm + NVOX + off[k]),   nsy);
            nsz = fmaf(wc[k], __ldg(g_norm + 2*NVOX + off[k]), nsz);
        }
        float nl = sqrtf(nsx*nsx + nsy*nsy + nsz*nsz);
        float ninv = -1.f / fmaxf(nl, 1e-12f);
        nsx *= ninv; nsy *= ninv; nsz *= ninv;
        float dt  = -(vx*nsx + vy*nsy + vz*nsz);
        float rx = fmaf(2.f*dt, nsx, vx);
        float ry = fmaf(2.f*dt, nsy, vy);
        float rz = fmaf(2.f*dt, nsz, vz);

        // layer 0 accumulators (64 neurons packed into 32 x f32x2)
        u64 h[32];
        {
            const ulonglong2* bp = (const ulonglong2*)(sh + OFF_B0);
            #pragma unroll
            for (int k=0; k<16; k++){
                ulonglong2 b2v = bp[k];
                h[2*k] = b2v.x; h[2*k+1] = b2v.y;
            }
        }

        // rgb latent channels 1..15
        for (int ch=1; ch<=15; ++ch){
            const float* gp = grid + ch*NVOX;
            float v = 0.f;
            #pragma unroll
            for (int k=0; k<8; k++) v = fmaf(wc[k], __ldg(gp + off[k]), v);
            accum_row(h, v, sh + OFF_W0 + (ch-1)*64);
        }

        accum_row(h, rx, sh + OFF_W0 + 15*64);
        accum_row(h, ry, sh + OFF_W0 + 16*64);
        accum_row(h, rz, sh + OFF_W0 + 17*64);

        for (int f=0; f<6; ++f){
            float fr = (float)(1 << f);
            #pragma unroll
            for (int k3=0; k3<3; k3++){
                float ang = (k3==0 ? rx : (k3==1 ? ry : rz)) * fr;
                float kk = rintf(ang * 0.15915494309189535f);
                float r2 = fmaf(kk, -6.283185307179586f, ang);
                float sn, cs;
                sincosf(r2, &sn, &cs);
                int rowi = 18 + f*3 + k3;
                accum_row(h, sn, sh + OFF_W0 + rowi*64);
                accum_row(h, cs, sh + OFF_W0 + (rowi+18)*64);
            }
        }

        // relu -> local stage
        #pragma unroll
        for (int k=0; k<32; k++){
            float flo, fhi; f2unpack(h[k], flo, fhi);
            stage[2*k]   = fmaxf(flo, 0.f);
            stage[2*k+1] = fmaxf(fhi, 0.f);
        }
        // layer 1 (reuse h as accumulators)
        {
            const ulonglong2* bp = (const ulonglong2*)(sh + OFF_B1);
            #pragma unroll
            for (int k=0; k<16; k++){
                ulonglong2 b2v = bp[k];
                h[2*k] = b2v.x; h[2*k+1] = b2v.y;
            }
        }
        for (int i=0; i<64; i++) accum_row(h, stage[i], sh + OFF_W1 + i*64);
        #pragma unroll
        for (int k=0; k<32; k++){
            float flo, fhi; f2unpack(h[k], flo, fhi);
            stage[2*k]   = fmaxf(flo, 0.f);
            stage[2*k+1] = fmaxf(fhi, 0.f);
        }
        // layer 2
        {
            const ulonglong2* bp = (const ulonglong2*)(sh + OFF_B2);
            #pragma unroll
            for (int k=0; k<16; k++){
                ulonglong2 b2v = bp[k];
                h[2*k] = b2v.x; h[2*k+1] = b2v.y;
            }
        }
        for (int i=0; i<64; i++) accum_row(h, stage[i], sh + OFF_W2 + i*64);
        #pragma unroll
        for (int k=0; k<32; k++){
            float flo, fhi; f2unpack(h[k], flo, fhi);
            stage[2*k]   = fmaxf(flo, 0.f);
            stage[2*k+1] = fmaxf(fhi, 0.f);
        }
        // layer 3 (64 -> 3) + sigmoid
        float c0s = sh[OFF_B3+0], c1s = sh[OFF_B3+1], c2s = sh[OFF_B3+2];
        for (int i=0; i<64; i++){
            float v = stage[i];
            c0s = fmaf(v, sh[OFF_W3 + i*3 + 0], c0s);
            c1s = fmaf(v, sh[OFF_W3 + i*3 + 1], c1s);
            c2s = fmaf(v, sh[OFF_W3 + i*3 + 2], c2s);
        }
        float col0 = 1.f / (1.f + expf(-c0s));
        float col1 = 1.f / (1.f + expf(-c1s));
        float col2 = 1.f / (1.f + expf(-c2s));
        g_c0[e] = wgt * col0;
        g_c1[e] = wgt * col1;
        g_c2[e] = wgt * col2;
    }
}

// ---------------------------------------------------------------------------
// Kernel 5: per-ray deterministic reduction + background.
// ---------------------------------------------------------------------------
__global__ void __launch_bounds__(32) reduce_kernel(float* __restrict__ out)
{
    int ray = blockIdx.x;
    int lane = threadIdx.x;
    int base = g_base[ray];
    int cnt  = g_base[ray+1] - base;
    float a0 = 0.f, a1 = 0.f, a2 = 0.f;
    for (int i=lane; i<cnt; i+=32){
        a0 += g_c0[base+i];
        a1 += g_c1[base+i];
        a2 += g_c2[base+i];
    }
    #pragma unroll
    for (int o=16; o; o>>=1){
        a0 += __shfl_down_sync(0xffffffffu, a0, o);
        a1 += __shfl_down_sync(0xffffffffu, a1, o);
        a2 += __shfl_down_sync(0xffffffffu, a2, o);
    }
    if (lane == 0){
        float Tf = g_T[ray];        // BG = 1.0
        out[ray*3+0] = a0 + Tf;
        out[ray*3+1] = a1 + Tf;
        out[ray*3+2] = a2 + Tf;
    }
}

extern "C" void kernel_launch(void* const* d_in, const int* in_sizes, int n_in,
                              void* d_out, int out_size)
{
    (void)in_sizes; (void)n_in; (void)out_size;
    const float* ro    = (const float*)d_in[0];
    const float* rd    = (const float*)d_in[1];
    const float* vd    = (const float*)d_in[2];
    const float* grid  = (const float*)d_in[3];
    const float* sobel = (const float*)d_in[4];
    const float* w0 = (const float*)d_in[5];
    const float* b0 = (const float*)d_in[6];
    const float* w1 = (const float*)d_in[7];
    const float* b1 = (const float*)d_in[8];
    const float* w2 = (const float*)d_in[9];
    const float* b2 = (const float*)d_in[10];
    const float* w3 = (const float*)d_in[11];
    const float* b3 = (const float*)d_in[12];
    float* out = (float*)d_out;

    conv_kernel<<<dim3(4,16,32), dim3(32,8,1)>>>(grid, sobel);
    prep_kernel<<<NRAYS, 128>>>(ro, rd, grid);
    scan_kernel<<<1, 1024>>>();

    static int smem_set = 0;
    if (!smem_set){
        cudaFuncSetAttribute(mlp_kernel,
                             cudaFuncAttributeMaxDynamicSharedMemorySize, SMEM_MLP);
        smem_set = 1;
    }
    mlp_kernel<<<MLP_BLOCKS, MLP_NTH, SMEM_MLP>>>(ro, rd, vd, grid,
                                                  w0, b0, w1, b1, w2, b2, w3, b3);
    reduce_kernel<<<NRAYS, 32>>>(out);
}

// round 4
// speedup vs baseline: 1.0863x; 1.0863x over previous
#include <cuda_runtime.h>
#include <math.h>

#define RESX   128
#define NVOX   (RESX*RESX*RESX)
#define NRAYS  1024
#define NS     891

#define ACT_SHIFT (-4.5951198501345898f)   // log(1/(1-0.01)-1)

// ---------------- global scratch (device globals: allowed) ----------------
__device__ float g_norm[3*NVOX];
__device__ float g_w[NRAYS*NS];
__device__ float g_T[NRAYS];
__device__ float g_tmin[NRAYS];
__device__ float g_invn[NRAYS];
__device__ int   g_sstart[NRAYS];
__device__ int   g_scnt[NRAYS];
__device__ int   g_base[NRAYS+1];
__device__ int   g_total;
__device__ float g_c0[NRAYS*NS];
__device__ float g_c1[NRAYS*NS];
__device__ float g_c2[NRAYS*NS];

// ---------------------------------------------------------------------------
// Kernel 1: 5x5x5 conv of density with sobel kernel, zero pad 2, normalize.
// ---------------------------------------------------------------------------
__global__ void __launch_bounds__(256) conv_kernel(const float* __restrict__ dens,
                                                   const float* __restrict__ kern)
{
    __shared__ float sk[375];
    __shared__ float tile[8*12*36];

    int tc = threadIdx.x;
    int tb = threadIdx.y;
    int tid = tb*32 + tc;
    int c0 = blockIdx.x*32;
    int b0 = blockIdx.y*8;
    int a0 = blockIdx.z*4;

    for (int i=tid; i<375; i+=256) sk[i] = kern[i];
    for (int i=tid; i<8*12*36; i+=256){
        int ic = i % 36; int r = i / 36; int ib = r % 12; int ia = r / 12;
        int ga = a0 - 2 + ia, gb = b0 - 2 + ib, gc = c0 - 2 + ic;
        float v = 0.f;
        if ((unsigned)ga < 128u && (unsigned)gb < 128u && (unsigned)gc < 128u)
            v = dens[(ga*128 + gb)*128 + gc];
        tile[i] = v;
    }
    __syncthreads();

    float s0[4] = {0,0,0,0}, s1[4] = {0,0,0,0}, s2[4] = {0,0,0,0};
    for (int db=0; db<5; db++){
        for (int dc=0; dc<5; dc++){
            float tv[8];
            #pragma unroll
            for (int ia=0; ia<8; ia++)
                tv[ia] = tile[(ia*12 + tb + db)*36 + tc + dc];
            #pragma unroll
            for (int da=0; da<5; da++){
                float k0 = sk[0*125 + da*25 + db*5 + dc];
                float k1 = sk[1*125 + da*25 + db*5 + dc];
                float k2 = sk[2*125 + da*25 + db*5 + dc];
                #pragma unroll
                for (int v=0; v<4; v++){
                    float x = tv[v+da];
                    s0[v] = fmaf(k0, x, s0[v]);
                    s1[v] = fmaf(k1, x, s1[v]);
                    s2[v] = fmaf(k2, x, s2[v]);
                }
            }
        }
    }
    #pragma unroll
    for (int v=0; v<4; v++){
        int idx = ((a0+v)*128 + (b0+tb))*128 + (c0+tc);
        float n0 = s0[v], n1 = s1[v], n2 = s2[v];
        float len = sqrtf(n0*n0 + n1*n1 + n2*n2);
        float inv = -1.f / fmaxf(len, 1e-12f);
        g_norm[idx]          = n0*inv;
        g_norm[NVOX + idx]   = n1*inv;
        g_norm[2*NVOX + idx] = n2*inv;
    }
}

// ---------------------------------------------------------------------------
// packed fp32x2 helpers
// ---------------------------------------------------------------------------
typedef unsigned long long u64;
__device__ __forceinline__ u64 f2pack(float lo, float hi){
    u64 r; asm("mov.b64 %0,{%1,%2};" : "=l"(r) : "f"(lo), "f"(hi)); return r;
}
__device__ __forceinline__ void f2unpack(u64 v, float& lo, float& hi){
    asm("mov.b64 {%0,%1},%2;" : "=f"(lo), "=f"(hi) : "l"(v));
}
__device__ __forceinline__ u64 ffma2(u64 a, u64 b, u64 c){
    u64 d; asm("fma.rn.f32x2 %0,%1,%2,%3;" : "=l"(d) : "l"(a), "l"(b), "l"(c)); return d;
}
__device__ __forceinline__ void accum_row(u64* h, float v, const float* row){
    u64 vv = f2pack(v, v);
    const ulonglong2* wr = (const ulonglong2*)row;
    #pragma unroll
    for (int k=0; k<16; k++){
        ulonglong2 w2 = wr[k];
        h[2*k]   = ffma2(vv, w2.x, h[2*k]);
        h[2*k+1] = ffma2(vv, w2.y, h[2*k+1]);
    }
}

__device__ __forceinline__ void tri_setup(float px, float py, float pz,
                                          int* off, float* w)
{
    float ga = (px + 1.f)*0.5f*127.f;
    float gb = (py + 1.f)*0.5f*127.f;
    float gc = (pz + 1.f)*0.5f*127.f;
    float fa0 = floorf(ga), fb0 = floorf(gb), fc0 = floorf(gc);
    float fa = ga - fa0, fb = gb - fb0, fc = gc - fc0;
    int a0 = min(max((int)fa0, 0), 127);
    int b0 = min(max((int)fb0, 0), 127);
    int c0 = min(max((int)fc0, 0), 127);
    int a1 = min(a0+1, 127), b1 = min(b0+1, 127), c1 = min(c0+1, 127);
    int A0 = a0*16384, A1 = a1*16384, B0 = b0*128, B1 = b1*128;
    off[0]=A0+B0+c0; off[1]=A0+B0+c1; off[2]=A0+B1+c0; off[3]=A0+B1+c1;
    off[4]=A1+B0+c0; off[5]=A1+B0+c1; off[6]=A1+B1+c0; off[7]=A1+B1+c1;
    float wa0 = 1.f-fa, wb0 = 1.f-fb, wc0 = 1.f-fc;
    w[0]=wa0*wb0*wc0; w[1]=wa0*wb0*fc; w[2]=wa0*fb*wc0; w[3]=wa0*fb*fc;
    w[4]=fa*wb0*wc0;  w[5]=fa*wb0*fc;  w[6]=fa*fb*wc0;  w[7]=fa*fb*fc;
}

// ---------------------------------------------------------------------------
// Kernel 2: per-ray prep.
// ---------------------------------------------------------------------------
__global__ void __launch_bounds__(128) prep_kernel(
    const float* __restrict__ ro, const float* __restrict__ rdv,
    const float* __restrict__ grid)
{
    __shared__ float aw[NS];
    __shared__ int s_min, s_max;
    int tid = threadIdx.x;
    int rid = blockIdx.x;
    if (tid == 0){ s_min = 0x7fffffff; s_max = -1; }
    __syncthreads();

    float ox = ro[rid*3+0], oy = ro[rid*3+1], oz = ro[rid*3+2];
    float dx = rdv[rid*3+0], dy = rdv[rid*3+1], dz = rdv[rid*3+2];

    float vecx = (dx == 0.f) ? 1e-6f : dx;
    float vecy = (dy == 0.f) ? 1e-6f : dy;
    float vecz = (dz == 0.f) ? 1e-6f : dz;
    float rax = ( 1.f - ox)/vecx, rbx = (-1.f - ox)/vecx;
    float ray_ = ( 1.f - oy)/vecy, rby = (-1.f - oy)/vecy;
    float raz = ( 1.f - oz)/vecz, rbz = (-1.f - oz)/vecz;
    float tmin = fmaxf(fmaxf(fminf(rax,rbx), fminf(ray_,rby)), fminf(raz,rbz));
    tmin = fminf(fmaxf(tmin, 0.2f), 3.0f);
    float tmax = fminf(fminf(fmaxf(rax,rbx), fmaxf(ray_,rby)), fmaxf(raz,rbz));
    tmax = fminf(fmaxf(tmax, 0.2f), 3.0f);
    bool maskray = (tmax <= tmin);
    float invn = 1.f / sqrtf(dx*dx + dy*dy + dz*dz);

    int lmin = 0x7fffffff, lmax = -1;
    for (int s=tid; s<NS; s+=128){
        float t  = tmin + (0.0078125f * (float)s) * invn;
        float px = fmaf(dx, t, ox), py = fmaf(dy, t, oy), pz = fmaf(dz, t, oz);
        bool in = (!maskray) &&
                  !(px < -1.f || px > 1.f || py < -1.f || py > 1.f || pz < -1.f || pz > 1.f);
        float a = 0.f;
        if (in){
            int off[8]; float wc[8];
            tri_setup(px, py, pz, off, wc);
            float l0 = 0.f;
            #pragma unroll
            for (int k=0; k<8; k++) l0 = fmaf(wc[k], __ldg(grid + off[k]), l0);
            float xs = l0 + ACT_SHIFT;
            float sp = fmaxf(xs, 0.f) + log1pf(expf(-fabsf(xs)));
            a = 1.f - expf(-sp*0.5f);
            lmin = min(lmin, s); lmax = max(lmax, s);
        }
        aw[s] = a;
    }
    if (lmax >= 0){ atomicMin(&s_min, lmin); atomicMax(&s_max, lmax); }
    __syncthreads();

    if (tid == 0){
        float T = 1.f;
        for (int s=0; s<NS; s++){
            float a = aw[s];
            aw[s] = a * T;
            T *= fmaxf(1.f - a, 1e-10f);
        }
        g_T[rid]    = T;
        g_tmin[rid] = tmin;
        g_invn[rid] = invn;
        int cnt = (s_max >= s_min) ? (s_max - s_min + 1) : 0;
        g_sstart[rid] = (cnt > 0) ? s_min : 0;
        g_scnt[rid]   = cnt;
    }
    __syncthreads();

    int smn = s_min, smx = s_max;
    if (smx >= smn){
        for (int s=smn+tid; s<=smx; s+=128)
            g_w[rid*NS + s] = aw[s];
    }
}

// ---------------------------------------------------------------------------
// Kernel 3: exclusive prefix sum over 1024 ray counts.
// ---------------------------------------------------------------------------
__global__ void __launch_bounds__(1024) scan_kernel()
{
    __shared__ int tmp[NRAYS];
    int t = threadIdx.x;
    tmp[t] = g_scnt[t];
    __syncthreads();
    for (int o=1; o<NRAYS; o<<=1){
        int a = (t >= o) ? tmp[t-o] : 0;
        __syncthreads();
        tmp[t] += a;
        __syncthreads();
    }
    g_base[t+1] = tmp[t];
    if (t == 0) g_base[0] = 0;
    if (t == NRAYS-1) g_total = tmp[t];
}

// ---------------------------------------------------------------------------
// Kernel 4: balanced MLP. ONE 384-thread block per SM: the 52 KB weight
// copy is amortized over 12 warps, shared relu staging (no spills),
// regs budget 170 (65536/384).
// ---------------------------------------------------------------------------
#define OFF_W0   0
#define OFF_B0   3456
#define OFF_W1   3520
#define OFF_B1   7616
#define OFF_W2   7680
#define OFF_B2   11776
#define OFF_W3   11840
#define OFF_B3   12032
#define OFF_BASE 12036
#define OFF_HST  13064
#define MLP_NTH  384
#define SH_FLOATS (13064 + MLP_NTH*65)
#define SMEM_MLP (SH_FLOATS*4)
#define MLP_BLOCKS 148

__global__ void __launch_bounds__(MLP_NTH, 1) mlp_kernel(
    const float* __restrict__ ro,  const float* __restrict__ rdv,
    const float* __restrict__ vdv, const float* __restrict__ grid,
    const float* __restrict__ w0,  const float* __restrict__ b0,
    const float* __restrict__ w1,  const float* __restrict__ b1,
    const float* __restrict__ w2,  const float* __restrict__ b2,
    const float* __restrict__ w3,  const float* __restrict__ b3)
{
    extern __shared__ float sh[];
    int tid = threadIdx.x;
    int* sbase = (int*)(sh + OFF_BASE);

    for (int i=tid; i<3456; i+=MLP_NTH) sh[OFF_W0+i] = w0[i];
    for (int i=tid; i<64;   i+=MLP_NTH) sh[OFF_B0+i] = b0[i];
    for (int i=tid; i<4096; i+=MLP_NTH) sh[OFF_W1+i] = w1[i];
    for (int i=tid; i<64;   i+=MLP_NTH) sh[OFF_B1+i] = b1[i];
    for (int i=tid; i<4096; i+=MLP_NTH) sh[OFF_W2+i] = w2[i];
    for (int i=tid; i<64;   i+=MLP_NTH) sh[OFF_B2+i] = b2[i];
    for (int i=tid; i<192;  i+=MLP_NTH) sh[OFF_W3+i] = w3[i];
    if (tid < 3) sh[OFF_B3+tid] = b3[tid];
    for (int i=tid; i<NRAYS+1; i+=MLP_NTH) sbase[i] = g_base[i];
    __syncthreads();

    int total = g_total;
    float* hst = sh + OFF_HST + tid*65;   // stride 65 -> conflict-free

    for (int e = blockIdx.x*MLP_NTH + tid; e < total; e += MLP_BLOCKS*MLP_NTH){
        // binary search: largest ray with sbase[ray] <= e
        int lo = 0, hi = NRAYS;
        while (hi - lo > 1){
            int mid = (lo + hi) >> 1;
            if (sbase[mid] <= e) lo = mid; else hi = mid;
        }
        int ray = lo;
        int s = g_sstart[ray] + (e - sbase[ray]);

        float ox = __ldg(ro+ray*3+0), oy = __ldg(ro+ray*3+1), oz = __ldg(ro+ray*3+2);
        float dx = __ldg(rdv+ray*3+0), dy = __ldg(rdv+ray*3+1), dz = __ldg(rdv+ray*3+2);
        float vx = __ldg(vdv+ray*3+0), vy = __ldg(vdv+ray*3+1), vz = __ldg(vdv+ray*3+2);
        float tmin = __ldg(&g_tmin[ray]);
        float invn = __ldg(&g_invn[ray]);
        float wgt  = __ldg(&g_w[ray*NS + s]);

        float t  = tmin + (0.0078125f * (float)s) * invn;
        float px = fmaf(dx, t, ox), py = fmaf(dy, t, oy), pz = fmaf(dz, t, oz);

        int off[8]; float wc[8];
        tri_setup(px, py, pz, off, wc);

        // normals trilinear, consumed immediately (no long-lived prefetch regs)
        float nsx = 0.f, nsy = 0.f, nsz = 0.f;
        #pragma unroll
        for (int k=0; k<8; k++){
            nsx = fmaf(wc[k], __ldg(g_norm + off[k]),          nsx);
            nsy = fmaf(wc[k], __ldg(g_norm + NVOX + off[k]),   nsy);
            nsz = fmaf(wc[k], __ldg(g_norm + 2*NVOX + off[k]), nsz);
        }
        float nl = sqrtf(nsx*nsx + nsy*nsy + nsz*nsz);
        float ninv = -1.f / fmaxf(nl, 1e-12f);
        nsx *= ninv; nsy *= ninv; nsz *= ninv;
        float dt  = -(vx*nsx + vy*nsy + vz*nsz);
        float rx = fmaf(2.f*dt, nsx, vx);
        float ry = fmaf(2.f*dt, nsy, vy);
        float rz = fmaf(2.f*dt, nsz, vz);

        // layer 0 accumulators
        u64 h[32];
        {
            const ulonglong2* bp = (const ulonglong2*)(sh + OFF_B0);
            #pragma unroll
            for (int k=0; k<16; k++){
                ulonglong2 b2v = bp[k];
                h[2*k] = b2v.x; h[2*k+1] = b2v.y;
            }
        }

        // rgb latent channels 1..15 with 1-ahead prefetch
        float cv[8];
        #pragma unroll
        for (int k=0; k<8; k++) cv[k] = __ldg(grid + NVOX + off[k]);
        for (int ch=1; ch<=15; ++ch){
            float nv[8];
            if (ch < 15){
                const float* gp = grid + (ch+1)*NVOX;
                #pragma unroll
                for (int k=0; k<8; k++) nv[k] = __ldg(gp + off[k]);
            }
            float v = 0.f;
            #pragma unroll
            for (int k=0; k<8; k++) v = fmaf(wc[k], cv[k], v);
            accum_row(h, v, sh + OFF_W0 + (ch-1)*64);
            if (ch < 15){
                #pragma unroll
                for (int k=0; k<8; k++) cv[k] = nv[k];
            }
        }

        accum_row(h, rx, sh + OFF_W0 + 15*64);
        accum_row(h, ry, sh + OFF_W0 + 16*64);
        accum_row(h, rz, sh + OFF_W0 + 17*64);

        for (int f=0; f<6; ++f){
            float fr = (float)(1 << f);
            #pragma unroll
            for (int k3=0; k3<3; k3++){
                float ang = (k3==0 ? rx : (k3==1 ? ry : rz)) * fr;
                float kk = rintf(ang * 0.15915494309189535f);
                float r2 = fmaf(kk, -6.283185307179586f, ang);
                float sn, cs;
                sincosf(r2, &sn, &cs);
                int rowi = 18 + f*3 + k3;
                accum_row(h, sn, sh + OFF_W0 + rowi*64);
                accum_row(h, cs, sh + OFF_W0 + (rowi+18)*64);
            }
        }

        // relu -> shared stage
        #pragma unroll
        for (int k=0; k<32; k++){
            float flo, fhi; f2unpack(h[k], flo, fhi);
            hst[2*k]   = fmaxf(flo, 0.f);
            hst[2*k+1] = fmaxf(fhi, 0.f);
        }
        // layer 1
        {
            const ulonglong2* bp = (const ulonglong2*)(sh + OFF_B1);
            #pragma unroll
            for (int k=0; k<16; k++){
                ulonglong2 b2v = bp[k];
                h[2*k] = b2v.x; h[2*k+1] = b2v.y;
            }
        }
        for (int i=0; i<64; i++) accum_row(h, hst[i], sh + OFF_W1 + i*64);
        #pragma unroll
        for (int k=0; k<32; k++){
            float flo, fhi; f2unpack(h[k], flo, fhi);
            hst[2*k]   = fmaxf(flo, 0.f);
            hst[2*k+1] = fmaxf(fhi, 0.f);
        }
        // layer 2
        {
            const ulonglong2* bp = (const ulonglong2*)(sh + OFF_B2);
            #pragma unroll
            for (int k=0; k<16; k++){
                ulonglong2 b2v = bp[k];
                h[2*k] = b2v.x; h[2*k+1] = b2v.y;
            }
        }
        for (int i=0; i<64; i++) accum_row(h, hst[i], sh + OFF_W2 + i*64);
        #pragma unroll
        for (int k=0; k<32; k++){
            float flo, fhi; f2unpack(h[k], flo, fhi);
            hst[2*k]   = fmaxf(flo, 0.f);
            hst[2*k+1] = fmaxf(fhi, 0.f);
        }
        // layer 3 + sigmoid
        float c0s = sh[OFF_B3+0], c1s = sh[OFF_B3+1], c2s = sh[OFF_B3+2];
        for (int i=0; i<64; i++){
            float v = hst[i];
            c0s = fmaf(v, sh[OFF_W3 + i*3 + 0], c0s);
            c1s = fmaf(v, sh[OFF_W3 + i*3 + 1], c1s);
            c2s = fmaf(v, sh[OFF_W3 + i*3 + 2], c2s);
        }
        float col0 = 1.f / (1.f + expf(-c0s));
        float col1 = 1.f / (1.f + expf(-c1s));
        float col2 = 1.f / (1.f + expf(-c2s));
        g_c0[e] = wgt * col0;
        g_c1[e] = wgt * col1;
        g_c2[e] = wgt * col2;
    }
}

// ---------------------------------------------------------------------------
// Kernel 5: per-ray deterministic reduction + background.
// ---------------------------------------------------------------------------
__global__ void __launch_bounds__(32) reduce_kernel(float* __restrict__ out)
{
    int ray = blockIdx.x;
    int lane = threadIdx.x;
    int base = g_base[ray];
    int cnt  = g_base[ray+1] - base;
    float a0 = 0.f, a1 = 0.f, a2 = 0.f;
    for (int i=lane; i<cnt; i+=32){
        a0 += g_c0[base+i];
        a1 += g_c1[base+i];
        a2 += g_c2[base+i];
    }
    #pragma unroll
    for (int o=16; o; o>>=1){
        a0 += __shfl_down_sync(0xffffffffu, a0, o);
        a1 += __shfl_down_sync(0xffffffffu, a1, o);
        a2 += __shfl_down_sync(0xffffffffu, a2, o);
    }
    if (lane == 0){
        float Tf = g_T[ray];        // BG = 1.0
        out[ray*3+0] = a0 + Tf;
        out[ray*3+1] = a1 + Tf;
        out[ray*3+2] = a2 + Tf;
    }
}

extern "C" void kernel_launch(void* const* d_in, const int* in_sizes, int n_in,
                              void* d_out, int out_size)
{
    (void)in_sizes; (void)n_in; (void)out_size;
    const float* ro    = (const float*)d_in[0];
    const float* rd    = (const float*)d_in[1];
    const float* vd    = (const float*)d_in[2];
    const float* grid  = (const float*)d_in[3];
    const float* sobel = (const float*)d_in[4];
    const float* w0 = (const float*)d_in[5];
    const float* b0 = (const float*)d_in[6];
    const float* w1 = (const float*)d_in[7];
    const float* b1 = (const float*)d_in[8];
    const float* w2 = (const float*)d_in[9];
    const float* b2 = (const float*)d_in[10];
    const float* w3 = (const float*)d_in[11];
    const float* b3 = (const float*)d_in[12];
    float* out = (float*)d_out;

    conv_kernel<<<dim3(4,16,32), dim3(32,8,1)>>>(grid, sobel);
    prep_kernel<<<NRAYS, 128>>>(ro, rd, grid);
    scan_kernel<<<1, 1024>>>();

    static int smem_set = 0;
    if (!smem_set){
        cudaFuncSetAttribute(mlp_kernel,
                             cudaFuncAttributeMaxDynamicSharedMemorySize, SMEM_MLP);
        smem_set = 1;
    }
    mlp_kernel<<<MLP_BLOCKS, MLP_NTH, SMEM_MLP>>>(ro, rd, vd, grid,
                                                  w0, b0, w1, b1, w2, b2, w3, b3);
    reduce_kernel<<<NRAYS, 32>>>(out);
}

// round 5
// speedup vs baseline: 1.1998x; 1.1045x over previous
#include <cuda_runtime.h>
#include <math.h>

#define RESX   128
#define NVOX   (RESX*RESX*RESX)
#define NRAYS  1024
#define NS     891

#define ACT_SHIFT (-4.5951198501345898f)

// ---------------- global scratch ----------------
__device__ float g_norm[3*NVOX];
__device__ float g_w[NRAYS*NS];
__device__ float g_T[NRAYS];
__device__ float g_tmin[NRAYS];
__device__ float g_invn[NRAYS];
__device__ int   g_sstart[NRAYS];
__device__ int   g_scnt[NRAYS];
__device__ int   g_base[NRAYS+1];
__device__ int   g_total;
__device__ int   g_work;
__device__ float g_c0[NRAYS*NS];
__device__ float g_c1[NRAYS*NS];
__device__ float g_c2[NRAYS*NS];

// ---------------------------------------------------------------------------
// packed fp32x2 helpers
// ---------------------------------------------------------------------------
typedef unsigned long long u64;
__device__ __forceinline__ u64 f2pack(float lo, float hi){
    u64 r; asm("mov.b64 %0,{%1,%2};" : "=l"(r) : "f"(lo), "f"(hi)); return r;
}
__device__ __forceinline__ void f2unpack(u64 v, float& lo, float& hi){
    asm("mov.b64 {%0,%1},%2;" : "=f"(lo), "=f"(hi) : "l"(v));
}
__device__ __forceinline__ u64 ffma2(u64 a, u64 b, u64 c){
    u64 d; asm("fma.rn.f32x2 %0,%1,%2,%3;" : "=l"(d) : "l"(a), "l"(b), "l"(c)); return d;
}
__device__ __forceinline__ void accum_row(u64* h, float v, const float* row){
    u64 vv = f2pack(v, v);
    const ulonglong2* wr = (const ulonglong2*)row;
    #pragma unroll
    for (int k=0; k<16; k++){
        ulonglong2 w2 = wr[k];
        h[2*k]   = ffma2(vv, w2.x, h[2*k]);
        h[2*k+1] = ffma2(vv, w2.y, h[2*k+1]);
    }
}

__device__ __forceinline__ void tri_setup(float px, float py, float pz,
                                          int* off, float* w)
{
    float ga = (px + 1.f)*0.5f*127.f;
    float gb = (py + 1.f)*0.5f*127.f;
    float gc = (pz + 1.f)*0.5f*127.f;
    float fa0 = floorf(ga), fb0 = floorf(gb), fc0 = floorf(gc);
    float fa = ga - fa0, fb = gb - fb0, fc = gc - fc0;
    int a0 = min(max((int)fa0, 0), 127);
    int b0 = min(max((int)fb0, 0), 127);
    int c0 = min(max((int)fc0, 0), 127);
    int a1 = min(a0+1, 127), b1 = min(b0+1, 127), c1 = min(c0+1, 127);
    int A0 = a0*16384, A1 = a1*16384, B0 = b0*128, B1 = b1*128;
    off[0]=A0+B0+c0; off[1]=A0+B0+c1; off[2]=A0+B1+c0; off[3]=A0+B1+c1;
    off[4]=A1+B0+c0; off[5]=A1+B0+c1; off[6]=A1+B1+c0; off[7]=A1+B1+c1;
    float wa0 = 1.f-fa, wb0 = 1.f-fb, wc0 = 1.f-fc;
    w[0]=wa0*wb0*wc0; w[1]=wa0*wb0*fc; w[2]=wa0*fb*wc0; w[3]=wa0*fb*fc;
    w[4]=fa*wb0*wc0;  w[5]=fa*wb0*fc;  w[6]=fa*fb*wc0;  w[7]=fa*fb*fc;
}

// ---------------------------------------------------------------------------
// Kernel 1: FUSED conv (blocks 0..2047) + prep (blocks 2048..3071).
// Independent work items run concurrently instead of serialized launches.
// ---------------------------------------------------------------------------
#define CONV_BLOCKS 2048
__global__ void __launch_bounds__(256) fused_kernel(
    const float* __restrict__ dens, const float* __restrict__ kern,
    const float* __restrict__ ro,   const float* __restrict__ rdv)
{
    __shared__ float smem_u[375 + 8*12*36];   // conv: sk+tile; prep: aw (891)
    __shared__ int s_min, s_max;

    if (blockIdx.x < CONV_BLOCKS){
        // ----------------- conv path -----------------
        float* sk   = smem_u;
        float* tile = smem_u + 375;
        int bid = blockIdx.x;
        int tc = threadIdx.x & 31;
        int tb = (threadIdx.x >> 5);          // 0..7
        int tid = threadIdx.x;
        int c0 = (bid & 3)*32;
        int b0 = ((bid >> 2) & 15)*8;
        int a0 = (bid >> 6)*4;

        for (int i=tid; i<375; i+=256) sk[i] = kern[i];
        for (int i=tid; i<8*12*36; i+=256){
            int ic = i % 36; int r = i / 36; int ib = r % 12; int ia = r / 12;
            int ga = a0 - 2 + ia, gb = b0 - 2 + ib, gc = c0 - 2 + ic;
            float v = 0.f;
            if ((unsigned)ga < 128u && (unsigned)gb < 128u && (unsigned)gc < 128u)
                v = dens[(ga*128 + gb)*128 + gc];
            tile[i] = v;
        }
        __syncthreads();

        float s0[4] = {0,0,0,0}, s1[4] = {0,0,0,0}, s2[4] = {0,0,0,0};
        for (int db=0; db<5; db++){
            for (int dc=0; dc<5; dc++){
                float tv[8];
                #pragma unroll
                for (int ia=0; ia<8; ia++)
                    tv[ia] = tile[(ia*12 + tb + db)*36 + tc + dc];
                #pragma unroll
                for (int da=0; da<5; da++){
                    float k0 = sk[0*125 + da*25 + db*5 + dc];
                    float k1 = sk[1*125 + da*25 + db*5 + dc];
                    float k2 = sk[2*125 + da*25 + db*5 + dc];
                    #pragma unroll
                    for (int v=0; v<4; v++){
                        float x = tv[v+da];
                        s0[v] = fmaf(k0, x, s0[v]);
                        s1[v] = fmaf(k1, x, s1[v]);
                        s2[v] = fmaf(k2, x, s2[v]);
                    }
                }
            }
        }
        #pragma unroll
        for (int v=0; v<4; v++){
            int idx = ((a0+v)*128 + (b0+tb))*128 + (c0+tc);
            float n0 = s0[v], n1 = s1[v], n2 = s2[v];
            float len = sqrtf(n0*n0 + n1*n1 + n2*n2);
            float inv = -1.f / fmaxf(len, 1e-12f);
            g_norm[idx]          = n0*inv;
            g_norm[NVOX + idx]   = n1*inv;
            g_norm[2*NVOX + idx] = n2*inv;
        }
    } else {
        // ----------------- prep path -----------------
        float* aw = smem_u;
        int tid = threadIdx.x;
        int rid = blockIdx.x - CONV_BLOCKS;
        if (tid == 0){ s_min = 0x7fffffff; s_max = -1; }
        __syncthreads();

        float ox = ro[rid*3+0], oy = ro[rid*3+1], oz = ro[rid*3+2];
        float dx = rdv[rid*3+0], dy = rdv[rid*3+1], dz = rdv[rid*3+2];

        float vecx = (dx == 0.f) ? 1e-6f : dx;
        float vecy = (dy == 0.f) ? 1e-6f : dy;
        float vecz = (dz == 0.f) ? 1e-6f : dz;
        float rax = ( 1.f - ox)/vecx, rbx = (-1.f - ox)/vecx;
        float ray_ = ( 1.f - oy)/vecy, rby = (-1.f - oy)/vecy;
        float raz = ( 1.f - oz)/vecz, rbz = (-1.f - oz)/vecz;
        float tmin = fmaxf(fmaxf(fminf(rax,rbx), fminf(ray_,rby)), fminf(raz,rbz));
        tmin = fminf(fmaxf(tmin, 0.2f), 3.0f);
        float tmax = fminf(fminf(fmaxf(rax,rbx), fmaxf(ray_,rby)), fmaxf(raz,rbz));
        tmax = fminf(fmaxf(tmax, 0.2f), 3.0f);
        bool maskray = (tmax <= tmin);
        float invn = 1.f / sqrtf(dx*dx + dy*dy + dz*dz);

        int lmin = 0x7fffffff, lmax = -1;
        for (int s=tid; s<NS; s+=256){
            float t  = tmin + (0.0078125f * (float)s) * invn;
            float px = fmaf(dx, t, ox), py = fmaf(dy, t, oy), pz = fmaf(dz, t, oz);
            bool in = (!maskray) &&
                      !(px < -1.f || px > 1.f || py < -1.f || py > 1.f || pz < -1.f || pz > 1.f);
            float a = 0.f;
            if (in){
                int off[8]; float wc[8];
                tri_setup(px, py, pz, off, wc);
                float l0 = 0.f;
                #pragma unroll
                for (int k=0; k<8; k++) l0 = fmaf(wc[k], __ldg(dens + off[k]), l0);
                float xs = l0 + ACT_SHIFT;
                float sp = fmaxf(xs, 0.f) + log1pf(expf(-fabsf(xs)));
                a = 1.f - expf(-sp*0.5f);
                lmin = min(lmin, s); lmax = max(lmax, s);
            }
            aw[s] = a;
        }
        if (lmax >= 0){ atomicMin(&s_min, lmin); atomicMax(&s_max, lmax); }
        __syncthreads();

        if (tid == 0){
            float T = 1.f;
            for (int s=0; s<NS; s++){
                float a = aw[s];
                aw[s] = a * T;
                T *= fmaxf(1.f - a, 1e-10f);
            }
            g_T[rid]    = T;
            g_tmin[rid] = tmin;
            g_invn[rid] = invn;
            int cnt = (s_max >= s_min) ? (s_max - s_min + 1) : 0;
            g_sstart[rid] = (cnt > 0) ? s_min : 0;
            g_scnt[rid]   = cnt;
        }
        __syncthreads();

        int smn = s_min, smx = s_max;
        if (smx >= smn){
            for (int s=smn+tid; s<=smx; s+=256)
                g_w[rid*NS + s] = aw[s];
        }
    }
}

// ---------------------------------------------------------------------------
// Kernel 2: shuffle-based exclusive scan over 1024 counts + work reset.
// ---------------------------------------------------------------------------
__global__ void __launch_bounds__(1024) scan_kernel()
{
    __shared__ int wsum[32];
    int t = threadIdx.x;
    int lane = t & 31, wid = t >> 5;
    int v = g_scnt[t];
    #pragma unroll
    for (int o=1; o<32; o<<=1){
        int n = __shfl_up_sync(0xffffffffu, v, o);
        if (lane >= o) v += n;
    }
    if (lane == 31) wsum[wid] = v;
    __syncthreads();
    if (wid == 0){
        int w = wsum[lane];
        #pragma unroll
        for (int o=1; o<32; o<<=1){
            int n = __shfl_up_sync(0xffffffffu, w, o);
            if (lane >= o) w += n;
        }
        wsum[lane] = w;
    }
    __syncthreads();
    if (wid > 0) v += wsum[wid-1];
    g_base[t+1] = v;
    if (t == 0){ g_base[0] = 0; g_work = 0; }
    if (t == 1023) g_total = v;
}

// ---------------------------------------------------------------------------
// Kernel 3: MLP with warp-level dynamic work stealing (32-entry chunks).
// 320 threads/block (reg budget 204), 148 persistent blocks.
// ---------------------------------------------------------------------------
#define OFF_W0   0
#define OFF_B0   3456
#define OFF_W1   3520
#define OFF_B1   7616
#define OFF_W2   7680
#define OFF_B2   11776
#define OFF_W3   11840
#define OFF_B3   12032
#define OFF_BASE 12036
#define OFF_HST  13064
#define MLP_NTH  320
#define SH_FLOATS (13064 + MLP_NTH*65)
#define SMEM_MLP (SH_FLOATS*4)
#define MLP_BLOCKS 148

__global__ void __launch_bounds__(MLP_NTH, 1) mlp_kernel(
    const float* __restrict__ ro,  const float* __restrict__ rdv,
    const float* __restrict__ vdv, const float* __restrict__ grid,
    const float* __restrict__ w0,  const float* __restrict__ b0,
    const float* __restrict__ w1,  const float* __restrict__ b1,
    const float* __restrict__ w2,  const float* __restrict__ b2,
    const float* __restrict__ w3,  const float* __restrict__ b3)
{
    extern __shared__ float sh[];
    int tid = threadIdx.x;
    int lane = tid & 31;
    int* sbase = (int*)(sh + OFF_BASE);

    for (int i=tid; i<3456; i+=MLP_NTH) sh[OFF_W0+i] = w0[i];
    for (int i=tid; i<64;   i+=MLP_NTH) sh[OFF_B0+i] = b0[i];
    for (int i=tid; i<4096; i+=MLP_NTH) sh[OFF_W1+i] = w1[i];
    for (int i=tid; i<64;   i+=MLP_NTH) sh[OFF_B1+i] = b1[i];
    for (int i=tid; i<4096; i+=MLP_NTH) sh[OFF_W2+i] = w2[i];
    for (int i=tid; i<64;   i+=MLP_NTH) sh[OFF_B2+i] = b2[i];
    for (int i=tid; i<192;  i+=MLP_NTH) sh[OFF_W3+i] = w3[i];
    if (tid < 3) sh[OFF_B3+tid] = b3[tid];
    for (int i=tid; i<NRAYS+1; i+=MLP_NTH) sbase[i] = g_base[i];
    __syncthreads();

    int total = g_total;
    int nchunks = (total + 31) >> 5;
    float* hst = sh + OFF_HST + tid*65;

    while (true){
        int chunk = 0;
        if (lane == 0) chunk = atomicAdd(&g_work, 1);
        chunk = __shfl_sync(0xffffffffu, chunk, 0);
        if (chunk >= nchunks) break;
        int e = chunk*32 + lane;
        bool valid = (e < total);
        int ec = valid ? e : (total - 1);

        // binary search: largest ray with sbase[ray] <= ec
        int lo = 0, hi = NRAYS;
        while (hi - lo > 1){
            int mid = (lo + hi) >> 1;
            if (sbase[mid] <= ec) lo = mid; else hi = mid;
        }
        int ray = lo;
        int s = g_sstart[ray] + (ec - sbase[ray]);

        float ox = __ldg(ro+ray*3+0), oy = __ldg(ro+ray*3+1), oz = __ldg(ro+ray*3+2);
        float dx = __ldg(rdv+ray*3+0), dy = __ldg(rdv+ray*3+1), dz = __ldg(rdv+ray*3+2);
        float vx = __ldg(vdv+ray*3+0), vy = __ldg(vdv+ray*3+1), vz = __ldg(vdv+ray*3+2);
        float tmin = __ldg(&g_tmin[ray]);
        float invn = __ldg(&g_invn[ray]);
        float wgt  = __ldg(&g_w[ray*NS + s]);

        float t  = tmin + (0.0078125f * (float)s) * invn;
        float px = fmaf(dx, t, ox), py = fmaf(dy, t, oy), pz = fmaf(dz, t, oz);

        int off[8]; float wc[8];
        tri_setup(px, py, pz, off, wc);

        // prefetch all 24 normal gathers early (latency overlap)
        float nvx[8], nvy[8], nvz[8];
        #pragma unroll
        for (int k=0; k<8; k++){
            nvx[k] = __ldg(g_norm + off[k]);
            nvy[k] = __ldg(g_norm + NVOX + off[k]);
            nvz[k] = __ldg(g_norm + 2*NVOX + off[k]);
        }

        // layer 0 accumulators
        u64 h[32];
        {
            const ulonglong2* bp = (const ulonglong2*)(sh + OFF_B0);
            #pragma unroll
            for (int k=0; k<16; k++){
                ulonglong2 b2v = bp[k];
                h[2*k] = b2v.x; h[2*k+1] = b2v.y;
            }
        }

        // rgb latent channels 1..15 with 1-ahead prefetch
        float cv[8];
        #pragma unroll
        for (int k=0; k<8; k++) cv[k] = __ldg(grid + NVOX + off[k]);
        for (int ch=1; ch<=15; ++ch){
            float nv[8];
            if (ch < 15){
                const float* gp = grid + (ch+1)*NVOX;
                #pragma unroll
                for (int k=0; k<8; k++) nv[k] = __ldg(gp + off[k]);
            }
            float v = 0.f;
            #pragma unroll
            for (int k=0; k<8; k++) v = fmaf(wc[k], cv[k], v);
            accum_row(h, v, sh + OFF_W0 + (ch-1)*64);
            if (ch < 15){
                #pragma unroll
                for (int k=0; k<8; k++) cv[k] = nv[k];
            }
        }

        // normals trilinear + renormalize + reflect
        float nsx = 0.f, nsy = 0.f, nsz = 0.f;
        #pragma unroll
        for (int k=0; k<8; k++){
            nsx = fmaf(wc[k], nvx[k], nsx);
            nsy = fmaf(wc[k], nvy[k], nsy);
            nsz = fmaf(wc[k], nvz[k], nsz);
        }
        float nl = sqrtf(nsx*nsx + nsy*nsy + nsz*nsz);
        float ninv = -1.f / fmaxf(nl, 1e-12f);
        nsx *= ninv; nsy *= ninv; nsz *= ninv;
        float dt  = -(vx*nsx + vy*nsy + vz*nsz);
        float rx = fmaf(2.f*dt, nsx, vx);
        float ry = fmaf(2.f*dt, nsy, vy);
        float rz = fmaf(2.f*dt, nsz, vz);

        accum_row(h, rx, sh + OFF_W0 + 15*64);
        accum_row(h, ry, sh + OFF_W0 + 16*64);
        accum_row(h, rz, sh + OFF_W0 + 17*64);

        for (int f=0; f<6; ++f){
            float fr = (float)(1 << f);
            #pragma unroll
            for (int k3=0; k3<3; k3++){
                float ang = (k3==0 ? rx : (k3==1 ? ry : rz)) * fr;
                float kk = rintf(ang * 0.15915494309189535f);
                float r2 = fmaf(kk, -6.283185307179586f, ang);
                float sn, cs;
                sincosf(r2, &sn, &cs);
                int rowi = 18 + f*3 + k3;
                accum_row(h, sn, sh + OFF_W0 + rowi*64);
                accum_row(h, cs, sh + OFF_W0 + (rowi+18)*64);
            }
        }

        // relu -> shared stage
        #pragma unroll
        for (int k=0; k<32; k++){
            float flo, fhi; f2unpack(h[k], flo, fhi);
            hst[2*k]   = fmaxf(flo, 0.f);
            hst[2*k+1] = fmaxf(fhi, 0.f);
        }
        // layer 1
        {
            const ulonglong2* bp = (const ulonglong2*)(sh + OFF_B1);
            #pragma unroll
            for (int k=0; k<16; k++){
                ulonglong2 b2v = bp[k];
                h[2*k] = b2v.x; h[2*k+1] = b2v.y;
            }
        }
        for (int i=0; i<64; i++) accum_row(h, hst[i], sh + OFF_W1 + i*64);
        #pragma unroll
        for (int k=0; k<32; k++){
            float flo, fhi; f2unpack(h[k], flo, fhi);
            hst[2*k]   = fmaxf(flo, 0.f);
            hst[2*k+1] = fmaxf(fhi, 0.f);
        }
        // layer 2
        {
            const ulonglong2* bp = (const ulonglong2*)(sh + OFF_B2);
            #pragma unroll
            for (int k=0; k<16; k++){
                ulonglong2 b2v = bp[k];
                h[2*k] = b2v.x; h[2*k+1] = b2v.y;
            }
        }
        for (int i=0; i<64; i++) accum_row(h, hst[i], sh + OFF_W2 + i*64);
        #pragma unroll
        for (int k=0; k<32; k++){
            float flo, fhi; f2unpack(h[k], flo, fhi);
            hst[2*k]   = fmaxf(flo, 0.f);
            hst[2*k+1] = fmaxf(fhi, 0.f);
        }
        // layer 3 + sigmoid
        float c0s = sh[OFF_B3+0], c1s = sh[OFF_B3+1], c2s = sh[OFF_B3+2];
        for (int i=0; i<64; i++){
            float v = hst[i];
            c0s = fmaf(v, sh[OFF_W3 + i*3 + 0], c0s);
            c1s = fmaf(v, sh[OFF_W3 + i*3 + 1], c1s);
            c2s = fmaf(v, sh[OFF_W3 + i*3 + 2], c2s);
        }
        float col0 = 1.f / (1.f + expf(-c0s));
        float col1 = 1.f / (1.f + expf(-c1s));
        float col2 = 1.f / (1.f + expf(-c2s));
        if (valid){
            g_c0[e] = wgt * col0;
            g_c1[e] = wgt * col1;
            g_c2[e] = wgt * col2;
        }
    }
}

// ---------------------------------------------------------------------------
// Kernel 4: per-ray deterministic reduction + background.
// ---------------------------------------------------------------------------
__global__ void __launch_bounds__(32) reduce_kernel(float* __restrict__ out)
{
    int ray = blockIdx.x;
    int lane = threadIdx.x;
    int base = g_base[ray];
    int cnt  = g_base[ray+1] - base;
    float a0 = 0.f, a1 = 0.f, a2 = 0.f;
    for (int i=lane; i<cnt; i+=32){
        a0 += g_c0[base+i];
        a1 += g_c1[base+i];
        a2 += g_c2[base+i];
    }
    #pragma unroll
    for (int o=16; o; o>>=1){
        a0 += __shfl_down_sync(0xffffffffu, a0, o);
        a1 += __shfl_down_sync(0xffffffffu, a1, o);
        a2 += __shfl_down_sync(0xffffffffu, a2, o);
    }
    if (lane == 0){
        float Tf = g_T[ray];
        out[ray*3+0] = a0 + Tf;
        out[ray*3+1] = a1 + Tf;
        out[ray*3+2] = a2 + Tf;
    }
}

extern "C" void kernel_launch(void* const* d_in, const int* in_sizes, int n_in,
                              void* d_out, int out_size)
{
    (void)in_sizes; (void)n_in; (void)out_size;
    const float* ro    = (const float*)d_in[0];
    const float* rd    = (const float*)d_in[1];
    const float* vd    = (const float*)d_in[2];
    const float* grid  = (const float*)d_in[3];
    const float* sobel = (const float*)d_in[4];
    const float* w0 = (const float*)d_in[5];
    const float* b0 = (const float*)d_in[6];
    const float* w1 = (const float*)d_in[7];
    const float* b1 = (const float*)d_in[8];
    const float* w2 = (const float*)d_in[9];
    const float* b2 = (const float*)d_in[10];
    const float* w3 = (const float*)d_in[11];
    const float* b3 = (const float*)d_in[12];
    float* out = (float*)d_out;

    fused_kernel<<<CONV_BLOCKS + NRAYS, 256>>>(grid, sobel, ro, rd);
    scan_kernel<<<1, 1024>>>();

    static int smem_set = 0;
    if (!smem_set){
        cudaFuncSetAttribute(mlp_kernel,
                             cudaFuncAttributeMaxDynamicSharedMemorySize, SMEM_MLP);
        smem_set = 1;
    }
    mlp_kernel<<<MLP_BLOCKS, MLP_NTH, SMEM_MLP>>>(ro, rd, vd, grid,
                                                  w0, b0, w1, b1, w2, b2, w3, b3);
    reduce_kernel<<<NRAYS, 32>>>(out);
}

// round 6
// speedup vs baseline: 1.3894x; 1.1580x over previous
#include <cuda_runtime.h>
#include <math.h>

#define RESX   128
#define NVOX   (RESX*RESX*RESX)
#define NRAYS  1024
#define NS     891

#define ACT_SHIFT (-4.5951198501345898f)

// ---------------- global scratch ----------------
__device__ float g_norm[3*NVOX];
__device__ float g_w[NRAYS*NS];
__device__ float g_T[NRAYS];
__device__ float g_tmin[NRAYS];
__device__ float g_invn[NRAYS];
__device__ int   g_sstart[NRAYS];
__device__ int   g_scnt[NRAYS];
__device__ int   g_base[NRAYS+1];
__device__ int   g_total;
__device__ int   g_work;
__device__ float g_c0[NRAYS*NS];
__device__ float g_c1[NRAYS*NS];
__device__ float g_c2[NRAYS*NS];

// ---------------------------------------------------------------------------
// packed fp32x2 helpers
// ---------------------------------------------------------------------------
typedef unsigned long long u64;
__device__ __forceinline__ u64 f2pack(float lo, float hi){
    u64 r; asm("mov.b64 %0,{%1,%2};" : "=l"(r) : "f"(lo), "f"(hi)); return r;
}
__device__ __forceinline__ void f2unpack(u64 v, float& lo, float& hi){
    asm("mov.b64 {%0,%1},%2;" : "=f"(lo), "=f"(hi) : "l"(v));
}
__device__ __forceinline__ u64 ffma2(u64 a, u64 b, u64 c){
    u64 d; asm("fma.rn.f32x2 %0,%1,%2,%3;" : "=l"(d) : "l"(a), "l"(b), "l"(c)); return d;
}

__device__ __forceinline__ void tri_setup(float px, float py, float pz,
                                          int* off, float* w)
{
    float ga = (px + 1.f)*0.5f*127.f;
    float gb = (py + 1.f)*0.5f*127.f;
    float gc = (pz + 1.f)*0.5f*127.f;
    float fa0 = floorf(ga), fb0 = floorf(gb), fc0 = floorf(gc);
    float fa = ga - fa0, fb = gb - fb0, fc = gc - fc0;
    int a0 = min(max((int)fa0, 0), 127);
    int b0 = min(max((int)fb0, 0), 127);
    int c0 = min(max((int)fc0, 0), 127);
    int a1 = min(a0+1, 127), b1 = min(b0+1, 127), c1 = min(c0+1, 127);
    int A0 = a0*16384, A1 = a1*16384, B0 = b0*128, B1 = b1*128;
    off[0]=A0+B0+c0; off[1]=A0+B0+c1; off[2]=A0+B1+c0; off[3]=A0+B1+c1;
    off[4]=A1+B0+c0; off[5]=A1+B0+c1; off[6]=A1+B1+c0; off[7]=A1+B1+c1;
    float wa0 = 1.f-fa, wb0 = 1.f-fb, wc0 = 1.f-fc;
    w[0]=wa0*wb0*wc0; w[1]=wa0*wb0*fc; w[2]=wa0*fb*wc0; w[3]=wa0*fb*fc;
    w[4]=fa*wb0*wc0;  w[5]=fa*wb0*fc;  w[6]=fa*fb*wc0;  w[7]=fa*fb*fc;
}

// ---------------------------------------------------------------------------
// Kernel 1: FUSED conv (blocks 0..2047) + prep (blocks 2048..3071).
// ---------------------------------------------------------------------------
#define CONV_BLOCKS 2048
__global__ void __launch_bounds__(256) fused_kernel(
    const float* __restrict__ dens, const float* __restrict__ kern,
    const float* __restrict__ ro,   const float* __restrict__ rdv)
{
    __shared__ float smem_u[375 + 8*12*36];
    __shared__ int s_min, s_max;

    if (blockIdx.x < CONV_BLOCKS){
        float* sk   = smem_u;
        float* tile = smem_u + 375;
        int bid = blockIdx.x;
        int tc = threadIdx.x & 31;
        int tb = (threadIdx.x >> 5);
        int tid = threadIdx.x;
        int c0 = (bid & 3)*32;
        int b0 = ((bid >> 2) & 15)*8;
        int a0 = (bid >> 6)*4;

        for (int i=tid; i<375; i+=256) sk[i] = kern[i];
        for (int i=tid; i<8*12*36; i+=256){
            int ic = i % 36; int r = i / 36; int ib = r % 12; int ia = r / 12;
            int ga = a0 - 2 + ia, gb = b0 - 2 + ib, gc = c0 - 2 + ic;
            float v = 0.f;
            if ((unsigned)ga < 128u && (unsigned)gb < 128u && (unsigned)gc < 128u)
                v = dens[(ga*128 + gb)*128 + gc];
            tile[i] = v;
        }
        __syncthreads();

        float s0[4] = {0,0,0,0}, s1[4] = {0,0,0,0}, s2[4] = {0,0,0,0};
        for (int db=0; db<5; db++){
            for (int dc=0; dc<5; dc++){
                float tv[8];
                #pragma unroll
                for (int ia=0; ia<8; ia++)
                    tv[ia] = tile[(ia*12 + tb + db)*36 + tc + dc];
                #pragma unroll
                for (int da=0; da<5; da++){
                    float k0 = sk[0*125 + da*25 + db*5 + dc];
                    float k1 = sk[1*125 + da*25 + db*5 + dc];
                    float k2 = sk[2*125 + da*25 + db*5 + dc];
                    #pragma unroll
                    for (int v=0; v<4; v++){
                        float x = tv[v+da];
                        s0[v] = fmaf(k0, x, s0[v]);
                        s1[v] = fmaf(k1, x, s1[v]);
                        s2[v] = fmaf(k2, x, s2[v]);
                    }
                }
            }
        }
        #pragma unroll
        for (int v=0; v<4; v++){
            int idx = ((a0+v)*128 + (b0+tb))*128 + (c0+tc);
            float n0 = s0[v], n1 = s1[v], n2 = s2[v];
            float len = sqrtf(n0*n0 + n1*n1 + n2*n2);
            float inv = -1.f / fmaxf(len, 1e-12f);
            g_norm[idx]          = n0*inv;
            g_norm[NVOX + idx]   = n1*inv;
            g_norm[2*NVOX + idx] = n2*inv;
        }
    } else {
        float* aw = smem_u;
        int tid = threadIdx.x;
        int rid = blockIdx.x - CONV_BLOCKS;
        if (tid == 0){ s_min = 0x7fffffff; s_max = -1; }
        __syncthreads();

        float ox = ro[rid*3+0], oy = ro[rid*3+1], oz = ro[rid*3+2];
        float dx = rdv[rid*3+0], dy = rdv[rid*3+1], dz = rdv[rid*3+2];

        float vecx = (dx == 0.f) ? 1e-6f : dx;
        float vecy = (dy == 0.f) ? 1e-6f : dy;
        float vecz = (dz == 0.f) ? 1e-6f : dz;
        float rax = ( 1.f - ox)/vecx, rbx = (-1.f - ox)/vecx;
        float ray_ = ( 1.f - oy)/vecy, rby = (-1.f - oy)/vecy;
        float raz = ( 1.f - oz)/vecz, rbz = (-1.f - oz)/vecz;
        float tmin = fmaxf(fmaxf(fminf(rax,rbx), fminf(ray_,rby)), fminf(raz,rbz));
        tmin = fminf(fmaxf(tmin, 0.2f), 3.0f);
        float tmax = fminf(fminf(fmaxf(rax,rbx), fmaxf(ray_,rby)), fmaxf(raz,rbz));
        tmax = fminf(fmaxf(tmax, 0.2f), 3.0f);
        bool maskray = (tmax <= tmin);
        float invn = 1.f / sqrtf(dx*dx + dy*dy + dz*dz);

        int lmin = 0x7fffffff, lmax = -1;
        for (int s=tid; s<NS; s+=256){
            float t  = tmin + (0.0078125f * (float)s) * invn;
            float px = fmaf(dx, t, ox), py = fmaf(dy, t, oy), pz = fmaf(dz, t, oz);
            bool in = (!maskray) &&
                      !(px < -1.f || px > 1.f || py < -1.f || py > 1.f || pz < -1.f || pz > 1.f);
            float a = 0.f;
            if (in){
                int off[8]; float wc[8];
                tri_setup(px, py, pz, off, wc);
                float l0 = 0.f;
                #pragma unroll
                for (int k=0; k<8; k++) l0 = fmaf(wc[k], __ldg(dens + off[k]), l0);
                float xs = l0 + ACT_SHIFT;
                float sp = fmaxf(xs, 0.f) + log1pf(expf(-fabsf(xs)));
                a = 1.f - expf(-sp*0.5f);
                lmin = min(lmin, s); lmax = max(lmax, s);
            }
            aw[s] = a;
        }
        if (lmax >= 0){ atomicMin(&s_min, lmin); atomicMax(&s_max, lmax); }
        __syncthreads();

        if (tid == 0){
            float T = 1.f;
            for (int s=0; s<NS; s++){
                float a = aw[s];
                aw[s] = a * T;
                T *= fmaxf(1.f - a, 1e-10f);
            }
            g_T[rid]    = T;
            g_tmin[rid] = tmin;
            g_invn[rid] = invn;
            int cnt = (s_max >= s_min) ? (s_max - s_min + 1) : 0;
            g_sstart[rid] = (cnt > 0) ? s_min : 0;
            g_scnt[rid]   = cnt;
        }
        __syncthreads();

        int smn = s_min, smx = s_max;
        if (smx >= smn){
            for (int s=smn+tid; s<=smx; s+=256)
                g_w[rid*NS + s] = aw[s];
        }
    }
}

// ---------------------------------------------------------------------------
// Kernel 2: shuffle-based exclusive scan + work reset.
// ---------------------------------------------------------------------------
__global__ void __launch_bounds__(1024) scan_kernel()
{
    __shared__ int wsum[32];
    int t = threadIdx.x;
    int lane = t & 31, wid = t >> 5;
    int v = g_scnt[t];
    #pragma unroll
    for (int o=1; o<32; o<<=1){
        int n = __shfl_up_sync(0xffffffffu, v, o);
        if (lane >= o) v += n;
    }
    if (lane == 31) wsum[wid] = v;
    __syncthreads();
    if (wid == 0){
        int w = wsum[lane];
        #pragma unroll
        for (int o=1; o<32; o<<=1){
            int n = __shfl_up_sync(0xffffffffu, w, o);
            if (lane >= o) w += n;
        }
        wsum[lane] = w;
    }
    __syncthreads();
    if (wid > 0) v += wsum[wid-1];
    g_base[t+1] = v;
    if (t == 0){ g_base[0] = 0; g_work = 0; }
    if (t == 1023) g_total = v;
}

// ---------------------------------------------------------------------------
// Kernel 3: pair-split MLP. Lane pair (2p,2p+1) handles 2 samples; each
// thread owns 32 neurons (its "half") for BOTH samples. Weight halves are
// stored +16B apart so even/odd lane LDS.128 resolve in ONE smem phase.
// Features/activations staged per-pair in shared (stride 130 words,
// conflict-free). Warp-level dynamic work stealing, 148 persistent blocks.
// ---------------------------------------------------------------------------
// shared layout (float offsets)
#define OFF_W0    0        // lo 54x32, pad 4, hi 54x32  -> 3460, pad 3464
#define OFF_W1    3464     // lo 64x32, pad 4, hi 64x32  -> 4100, pad 4104
#define OFF_W2    7568
#define OFF_W3    11672    // 192
#define OFF_B0    11864
#define OFF_B1    11928
#define OFF_B2    11992
#define OFF_B3    12056    // 3, pad to 12060
#define OFF_BASE  12060    // 1025 ints -> 13085, pad 13088
#define OFF_STAGE 13088    // 192 pairs * 130 floats = 24960
#define MLP_NTH   384
#define SH_FLOATS (OFF_STAGE + (MLP_NTH/2)*130)
#define SMEM_MLP  (SH_FLOATS*4)
#define MLP_BLOCKS 148

// GEMV over R rows: both samples of the pair, this thread's 32 neurons.
__device__ __forceinline__ void gemv_pair(u64* hA, u64* hB,
                                          const float* wbase,
                                          const float* fp, int R)
{
    for (int i=0; i<R; i++){
        float2 vp = *(const float2*)(fp + i*2);
        u64 vvA = f2pack(vp.x, vp.x);
        u64 vvB = f2pack(vp.y, vp.y);
        const ulonglong2* wr = (const ulonglong2*)(wbase + i*32);
        #pragma unroll
        for (int k=0; k<8; k++){
            ulonglong2 w2 = wr[k];
            hA[2*k]   = ffma2(vvA, w2.x, hA[2*k]);
            hA[2*k+1] = ffma2(vvA, w2.y, hA[2*k+1]);
            hB[2*k]   = ffma2(vvB, w2.x, hB[2*k]);
            hB[2*k+1] = ffma2(vvB, w2.y, hB[2*k+1]);
        }
    }
}

__device__ __forceinline__ void bias_init(u64* hA, u64* hB,
                                          const float* bias, int hf)
{
    const u64* bp = (const u64*)bias;
    #pragma unroll
    for (int k=0; k<16; k++){ u64 bb = bp[hf*16 + k]; hA[k]=bb; hB[k]=bb; }
}

__device__ __forceinline__ void relu_stage(const u64* hA, const u64* hB,
                                           float* fp, int hf)
{
    #pragma unroll
    for (int k=0; k<16; k++){
        float a0,a1,b0,b1;
        f2unpack(hA[k], a0, a1);
        f2unpack(hB[k], b0, b1);
        a0 = fmaxf(a0,0.f); a1 = fmaxf(a1,0.f);
        b0 = fmaxf(b0,0.f); b1 = fmaxf(b1,0.f);
        int n = hf*32 + 2*k;
        *(float2*)(fp + n*2)     = make_float2(a0, b0);
        *(float2*)(fp + n*2 + 2) = make_float2(a1, b1);
    }
}

__global__ void __launch_bounds__(MLP_NTH, 1) mlp_kernel(
    const float* __restrict__ ro,  const float* __restrict__ rdv,
    const float* __restrict__ vdv, const float* __restrict__ grid,
    const float* __restrict__ w0,  const float* __restrict__ b0,
    const float* __restrict__ w1,  const float* __restrict__ b1,
    const float* __restrict__ w2,  const float* __restrict__ b2,
    const float* __restrict__ w3,  const float* __restrict__ b3)
{
    extern __shared__ float sh[];
    int tid  = threadIdx.x;
    int lane = tid & 31;
    int hf   = tid & 1;            // half: 0 = neurons 0-31, 1 = 32-63
    int pg   = tid >> 1;           // block-local pair id
    int* sbase = (int*)(sh + OFF_BASE);

    // cooperative loads; w0/w1/w2 in split layout (hi half at +16B bank shift)
    for (int i=tid; i<54*64; i+=MLP_NTH){
        int r = i>>6, j = i&63;
        int dst = (j<32) ? (r*32+j) : (54*32+4 + r*32 + (j-32));
        sh[OFF_W0+dst] = w0[i];
    }
    for (int i=tid; i<64*64; i+=MLP_NTH){
        int r = i>>6, j = i&63;
        int dst = (j<32) ? (r*32+j) : (64*32+4 + r*32 + (j-32));
        sh[OFF_W1+dst] = w1[i];
        sh[OFF_W2+dst] = w2[i];
    }
    for (int i=tid; i<192; i+=MLP_NTH) sh[OFF_W3+i] = w3[i];
    for (int i=tid; i<64;  i+=MLP_NTH){
        sh[OFF_B0+i]=b0[i]; sh[OFF_B1+i]=b1[i]; sh[OFF_B2+i]=b2[i];
    }
    if (tid < 3) sh[OFF_B3+tid] = b3[tid];
    for (int i=tid; i<NRAYS+1; i+=MLP_NTH) sbase[i] = g_base[i];
    __syncthreads();

    int total   = g_total;
    int nchunks = (total + 31) >> 5;
    float* fp = sh + OFF_STAGE + pg*130;
    const float* wl0 = sh + OFF_W0 + hf*(54*32+4);
    const float* wl1 = sh + OFF_W1 + hf*(64*32+4);
    const float* wl2 = sh + OFF_W2 + hf*(64*32+4);

    while (true){
        int chunk = 0;
        if (lane == 0) chunk = atomicAdd(&g_work, 1);
        chunk = __shfl_sync(0xffffffffu, chunk, 0);
        if (chunk >= nchunks) break;
        int e = chunk*32 + lane;
        bool valid = (e < total);
        int ec = valid ? e : (total - 1);

        // ---- feature build for own sample ----
        int lo = 0, hi = NRAYS;
        while (hi - lo > 1){
            int mid = (lo + hi) >> 1;
            if (sbase[mid] <= ec) lo = mid; else hi = mid;
        }
        int ray = lo;
        int s = g_sstart[ray] + (ec - sbase[ray]);

        float ox = __ldg(ro+ray*3+0), oy = __ldg(ro+ray*3+1), oz = __ldg(ro+ray*3+2);
        float dx = __ldg(rdv+ray*3+0), dy = __ldg(rdv+ray*3+1), dz = __ldg(rdv+ray*3+2);
        float vx = __ldg(vdv+ray*3+0), vy = __ldg(vdv+ray*3+1), vz = __ldg(vdv+ray*3+2);
        float tmin = __ldg(&g_tmin[ray]);
        float invn = __ldg(&g_invn[ray]);
        float wgt  = __ldg(&g_w[ray*NS + s]);

        float t  = tmin + (0.0078125f * (float)s) * invn;
        float px = fmaf(dx, t, ox), py = fmaf(dy, t, oy), pz = fmaf(dz, t, oz);

        int off[8]; float wc[8];
        tri_setup(px, py, pz, off, wc);

        // normals gathers (issued early, 24 outstanding)
        float nvx[8], nvy[8], nvz[8];
        #pragma unroll
        for (int k=0; k<8; k++){
            nvx[k] = __ldg(g_norm + off[k]);
            nvy[k] = __ldg(g_norm + NVOX + off[k]);
            nvz[k] = __ldg(g_norm + 2*NVOX + off[k]);
        }

        // latents ch1..15 -> features 0..14
        for (int ch=1; ch<=15; ++ch){
            const float* gp = grid + ch*NVOX;
            float v = 0.f;
            #pragma unroll
            for (int k=0; k<8; k++) v = fmaf(wc[k], __ldg(gp + off[k]), v);
            fp[(ch-1)*2 + hf] = v;
        }

        float nsx = 0.f, nsy = 0.f, nsz = 0.f;
        #pragma unroll
        for (int k=0; k<8; k++){
            nsx = fmaf(wc[k], nvx[k], nsx);
            nsy = fmaf(wc[k], nvy[k], nsy);
            nsz = fmaf(wc[k], nvz[k], nsz);
        }
        float nl = sqrtf(nsx*nsx + nsy*nsy + nsz*nsz);
        float ninv = -1.f / fmaxf(nl, 1e-12f);
        nsx *= ninv; nsy *= ninv; nsz *= ninv;
        float dt  = -(vx*nsx + vy*nsy + vz*nsz);
        float rx = fmaf(2.f*dt, nsx, vx);
        float ry = fmaf(2.f*dt, nsy, vy);
        float rz = fmaf(2.f*dt, nsz, vz);
        fp[15*2 + hf] = rx;
        fp[16*2 + hf] = ry;
        fp[17*2 + hf] = rz;

        for (int f=0; f<6; ++f){
            float fr = (float)(1 << f);
            #pragma unroll
            for (int k3=0; k3<3; k3++){
                float ang = (k3==0 ? rx : (k3==1 ? ry : rz)) * fr;
                float kk = rintf(ang * 0.15915494309189535f);
                float r2 = fmaf(kk, -6.283185307179586f, ang);
                float sn, cs;
                sincosf(r2, &sn, &cs);
                fp[(18 + f*3 + k3)*2 + hf] = sn;
                fp[(36 + f*3 + k3)*2 + hf] = cs;
            }
        }
        __syncwarp();

        // ---- layer 0 (54 -> 64) ----
        u64 hA[16], hB[16];
        bias_init(hA, hB, sh + OFF_B0, hf);
        gemv_pair(hA, hB, wl0, fp, 54);
        __syncwarp();
        relu_stage(hA, hB, fp, hf);
        __syncwarp();

        // ---- layer 1 (64 -> 64) ----
        bias_init(hA, hB, sh + OFF_B1, hf);
        gemv_pair(hA, hB, wl1, fp, 64);
        __syncwarp();
        relu_stage(hA, hB, fp, hf);
        __syncwarp();

        // ---- layer 2 (64 -> 64) ----
        bias_init(hA, hB, sh + OFF_B2, hf);
        gemv_pair(hA, hB, wl2, fp, 64);

        // ---- layer 3 (64 -> 3): partials from own 32 neurons, relu in regs
        float pA0=0.f,pA1=0.f,pA2=0.f,pB0=0.f,pB1=0.f,pB2=0.f;
        #pragma unroll
        for (int k=0; k<16; k++){
            float a0,a1,b0v,b1v;
            f2unpack(hA[k], a0, a1);
            f2unpack(hB[k], b0v, b1v);
            a0 = fmaxf(a0,0.f); a1 = fmaxf(a1,0.f);
            b0v = fmaxf(b0v,0.f); b1v = fmaxf(b1v,0.f);
            int n0 = hf*32 + 2*k;
            float q00 = sh[OFF_W3 + n0*3 + 0];
            float q01 = sh[OFF_W3 + n0*3 + 1];
            float q02 = sh[OFF_W3 + n0*3 + 2];
            float q10 = sh[OFF_W3 + n0*3 + 3];
            float q11 = sh[OFF_W3 + n0*3 + 4];
            float q12 = sh[OFF_W3 + n0*3 + 5];
            pA0 = fmaf(a0,q00, fmaf(a1,q10, pA0));
            pA1 = fmaf(a0,q01, fmaf(a1,q11, pA1));
            pA2 = fmaf(a0,q02, fmaf(a1,q12, pA2));
            pB0 = fmaf(b0v,q00, fmaf(b1v,q10, pB0));
            pB1 = fmaf(b0v,q01, fmaf(b1v,q11, pB1));
            pB2 = fmaf(b0v,q02, fmaf(b1v,q12, pB2));
        }
        // combine halves within pair (commutative add -> identical on both)
        pA0 += __shfl_xor_sync(0xffffffffu, pA0, 1);
        pA1 += __shfl_xor_sync(0xffffffffu, pA1, 1);
        pA2 += __shfl_xor_sync(0xffffffffu, pA2, 1);
        pB0 += __shfl_xor_sync(0xffffffffu, pB0, 1);
        pB1 += __shfl_xor_sync(0xffffffffu, pB1, 1);
        pB2 += __shfl_xor_sync(0xffffffffu, pB2, 1);

        float c0s = (hf ? pB0 : pA0) + sh[OFF_B3+0];
        float c1s = (hf ? pB1 : pA1) + sh[OFF_B3+1];
        float c2s = (hf ? pB2 : pA2) + sh[OFF_B3+2];
        float col0 = 1.f / (1.f + expf(-c0s));
        float col1 = 1.f / (1.f + expf(-c1s));
        float col2 = 1.f / (1.f + expf(-c2s));
        if (valid){
            g_c0[e] = wgt * col0;
            g_c1[e] = wgt * col1;
            g_c2[e] = wgt * col2;
        }
    }
}

// ---------------------------------------------------------------------------
// Kernel 4: per-ray deterministic reduction + background.
// ---------------------------------------------------------------------------
__global__ void __launch_bounds__(32) reduce_kernel(float* __restrict__ out)
{
    int ray = blockIdx.x;
    int lane = threadIdx.x;
    int base = g_base[ray];
    int cnt  = g_base[ray+1] - base;
    float a0 = 0.f, a1 = 0.f, a2 = 0.f;
    for (int i=lane; i<cnt; i+=32){
        a0 += g_c0[base+i];
        a1 += g_c1[base+i];
        a2 += g_c2[base+i];
    }
    #pragma unroll
    for (int o=16; o; o>>=1){
        a0 += __shfl_down_sync(0xffffffffu, a0, o);
        a1 += __shfl_down_sync(0xffffffffu, a1, o);
        a2 += __shfl_down_sync(0xffffffffu, a2, o);
    }
    if (lane == 0){
        float Tf = g_T[ray];
        out[ray*3+0] = a0 + Tf;
        out[ray*3+1] = a1 + Tf;
        out[ray*3+2] = a2 + Tf;
    }
}

extern "C" void kernel_launch(void* const* d_in, const int* in_sizes, int n_in,
                              void* d_out, int out_size)
{
    (void)in_sizes; (void)n_in; (void)out_size;
    const float* ro    = (const float*)d_in[0];
    const float* rd    = (const float*)d_in[1];
    const float* vd    = (const float*)d_in[2];
    const float* grid  = (const float*)d_in[3];
    const float* sobel = (const float*)d_in[4];
    const float* w0 = (const float*)d_in[5];
    const float* b0 = (const float*)d_in[6];
    const float* w1 = (const float*)d_in[7];
    const float* b1 = (const float*)d_in[8];
    const float* w2 = (const float*)d_in[9];
    const float* b2 = (const float*)d_in[10];
    const float* w3 = (const float*)d_in[11];
    const float* b3 = (const float*)d_in[12];
    float* out = (float*)d_out;

    fused_kernel<<<CONV_BLOCKS + NRAYS, 256>>>(grid, sobel, ro, rd);
    scan_kernel<<<1, 1024>>>();

    static int smem_set = 0;
    if (!smem_set){
        cudaFuncSetAttribute(mlp_kernel,
                             cudaFuncAttributeMaxDynamicSharedMemorySize, SMEM_MLP);
        smem_set = 1;
    }
    mlp_kernel<<<MLP_BLOCKS, MLP_NTH, SMEM_MLP>>>(ro, rd, vd, grid,
                                                  w0, b0, w1, b1, w2, b2, w3, b3);
    reduce_kernel<<<NRAYS, 32>>>(out);
}

// round 7
// speedup vs baseline: 1.4495x; 1.0432x over previous
#include <cuda_runtime.h>
#include <math.h>

#define RESX   128
#define NVOX   (RESX*RESX*RESX)
#define NRAYS  1024
#define NS     891

#define ACT_SHIFT (-4.5951198501345898f)

// ---------------- global scratch ----------------
__device__ float g_norm[3*NVOX];
__device__ float g_w[NRAYS*NS];
__device__ float g_T[NRAYS];
__device__ float g_tmin[NRAYS];
__device__ float g_invn[NRAYS];
__device__ int   g_sstart[NRAYS];
__device__ int   g_scnt[NRAYS];
__device__ int   g_base[NRAYS+1];
__device__ int   g_total;
__device__ int   g_work;
__device__ float g_c0[NRAYS*NS];
__device__ float g_c1[NRAYS*NS];
__device__ float g_c2[NRAYS*NS];

// ---------------------------------------------------------------------------
// packed fp32x2 helpers
// ---------------------------------------------------------------------------
typedef unsigned long long u64;
__device__ __forceinline__ u64 f2pack(float lo, float hi){
    u64 r; asm("mov.b64 %0,{%1,%2};" : "=l"(r) : "f"(lo), "f"(hi)); return r;
}
__device__ __forceinline__ void f2unpack(u64 v, float& lo, float& hi){
    asm("mov.b64 {%0,%1},%2;" : "=f"(lo), "=f"(hi) : "l"(v));
}
__device__ __forceinline__ u64 ffma2(u64 a, u64 b, u64 c){
    u64 d; asm("fma.rn.f32x2 %0,%1,%2,%3;" : "=l"(d) : "l"(a), "l"(b), "l"(c)); return d;
}

__device__ __forceinline__ void tri_setup(float px, float py, float pz,
                                          int* off, float* w)
{
    float ga = (px + 1.f)*0.5f*127.f;
    float gb = (py + 1.f)*0.5f*127.f;
    float gc = (pz + 1.f)*0.5f*127.f;
    float fa0 = floorf(ga), fb0 = floorf(gb), fc0 = floorf(gc);
    float fa = ga - fa0, fb = gb - fb0, fc = gc - fc0;
    int a0 = min(max((int)fa0, 0), 127);
    int b0 = min(max((int)fb0, 0), 127);
    int c0 = min(max((int)fc0, 0), 127);
    int a1 = min(a0+1, 127), b1 = min(b0+1, 127), c1 = min(c0+1, 127);
    int A0 = a0*16384, A1 = a1*16384, B0 = b0*128, B1 = b1*128;
    off[0]=A0+B0+c0; off[1]=A0+B0+c1; off[2]=A0+B1+c0; off[3]=A0+B1+c1;
    off[4]=A1+B0+c0; off[5]=A1+B0+c1; off[6]=A1+B1+c0; off[7]=A1+B1+c1;
    float wa0 = 1.f-fa, wb0 = 1.f-fb, wc0 = 1.f-fc;
    w[0]=wa0*wb0*wc0; w[1]=wa0*wb0*fc; w[2]=wa0*fb*wc0; w[3]=wa0*fb*fc;
    w[4]=fa*wb0*wc0;  w[5]=fa*wb0*fc;  w[6]=fa*fb*wc0;  w[7]=fa*fb*fc;
}

// ---------------------------------------------------------------------------
// Kernel 1: FUSED conv (blocks 0..2047, f32x2-packed) + prep (2048..3071,
// parallel transmittance scan).
// ---------------------------------------------------------------------------
#define CONV_BLOCKS 2048
__global__ void __launch_bounds__(256) fused_kernel(
    const float* __restrict__ dens, const float* __restrict__ kern,
    const float* __restrict__ ro,   const float* __restrict__ rdv)
{
    __shared__ float smem_u[375 + 8*12*36];
    __shared__ float s_wprod[8];
    __shared__ int s_min, s_max;

    if (blockIdx.x < CONV_BLOCKS){
        // ----------------- conv path (packed f32x2, bit-exact) -----------------
        float* sk   = smem_u;
        float* tile = smem_u + 375;
        int bid = blockIdx.x;
        int tc = threadIdx.x & 31;
        int tb = (threadIdx.x >> 5);
        int tid = threadIdx.x;
        int c0 = (bid & 3)*32;
        int b0 = ((bid >> 2) & 15)*8;
        int a0 = (bid >> 6)*4;

        for (int i=tid; i<375; i+=256) sk[i] = kern[i];
        for (int i=tid; i<8*12*36; i+=256){
            int ic = i % 36; int r = i / 36; int ib = r % 12; int ia = r / 12;
            int ga = a0 - 2 + ia, gb = b0 - 2 + ib, gc = c0 - 2 + ic;
            float v = 0.f;
            if ((unsigned)ga < 128u && (unsigned)gb < 128u && (unsigned)gc < 128u)
                v = dens[(ga*128 + gb)*128 + gc];
            tile[i] = v;
        }
        __syncthreads();

        // accumulators: (v0,v1) and (v2,v3) packed per channel
        u64 s0p[2]={0,0}, s1p[2]={0,0}, s2p[2]={0,0};
        for (int db=0; db<5; db++){
            for (int dc=0; dc<5; dc++){
                float tv[8];
                #pragma unroll
                for (int ia=0; ia<8; ia++)
                    tv[ia] = tile[(ia*12 + tb + db)*36 + tc + dc];
                u64 p[7];
                #pragma unroll
                for (int i=0; i<7; i++) p[i] = f2pack(tv[i], tv[i+1]);
                #pragma unroll
                for (int da=0; da<5; da++){
                    float k0 = sk[0*125 + da*25 + db*5 + dc];
                    float k1 = sk[1*125 + da*25 + db*5 + dc];
                    float k2 = sk[2*125 + da*25 + db*5 + dc];
                    u64 kp0 = f2pack(k0,k0), kp1 = f2pack(k1,k1), kp2 = f2pack(k2,k2);
                    s0p[0] = ffma2(kp0, p[da],   s0p[0]);
                    s0p[1] = ffma2(kp0, p[da+2], s0p[1]);
                    s1p[0] = ffma2(kp1, p[da],   s1p[0]);
                    s1p[1] = ffma2(kp1, p[da+2], s1p[1]);
                    s2p[0] = ffma2(kp2, p[da],   s2p[0]);
                    s2p[1] = ffma2(kp2, p[da+2], s2p[1]);
                }
            }
        }
        float s0[4], s1[4], s2[4];
        f2unpack(s0p[0], s0[0], s0[1]); f2unpack(s0p[1], s0[2], s0[3]);
        f2unpack(s1p[0], s1[0], s1[1]); f2unpack(s1p[1], s1[2], s1[3]);
        f2unpack(s2p[0], s2[0], s2[1]); f2unpack(s2p[1], s2[2], s2[3]);
        #pragma unroll
        for (int v=0; v<4; v++){
            int idx = ((a0+v)*128 + (b0+tb))*128 + (c0+tc);
            float n0 = s0[v], n1 = s1[v], n2 = s2[v];
            float len = sqrtf(n0*n0 + n1*n1 + n2*n2);
            float inv = -1.f / fmaxf(len, 1e-12f);
            g_norm[idx]          = n0*inv;
            g_norm[NVOX + idx]   = n1*inv;
            g_norm[2*NVOX + idx] = n2*inv;
        }
    } else {
        // ----------------- prep path -----------------
        float* aw = smem_u;
        int tid = threadIdx.x;
        int lane = tid & 31, wid = tid >> 5;
        int rid = blockIdx.x - CONV_BLOCKS;
        if (tid == 0){ s_min = 0x7fffffff; s_max = -1; }
        __syncthreads();

        float ox = ro[rid*3+0], oy = ro[rid*3+1], oz = ro[rid*3+2];
        float dx = rdv[rid*3+0], dy = rdv[rid*3+1], dz = rdv[rid*3+2];

        float vecx = (dx == 0.f) ? 1e-6f : dx;
        float vecy = (dy == 0.f) ? 1e-6f : dy;
        float vecz = (dz == 0.f) ? 1e-6f : dz;
        float rax = ( 1.f - ox)/vecx, rbx = (-1.f - ox)/vecx;
        float ray_ = ( 1.f - oy)/vecy, rby = (-1.f - oy)/vecy;
        float raz = ( 1.f - oz)/vecz, rbz = (-1.f - oz)/vecz;
        float tmin = fmaxf(fmaxf(fminf(rax,rbx), fminf(ray_,rby)), fminf(raz,rbz));
        tmin = fminf(fmaxf(tmin, 0.2f), 3.0f);
        float tmax = fminf(fminf(fmaxf(rax,rbx), fmaxf(ray_,rby)), fmaxf(raz,rbz));
        tmax = fminf(fmaxf(tmax, 0.2f), 3.0f);
        bool maskray = (tmax <= tmin);
        float invn = 1.f / sqrtf(dx*dx + dy*dy + dz*dz);

        int lmin = 0x7fffffff, lmax = -1;
        for (int s=tid; s<NS; s+=256){
            float t  = tmin + (0.0078125f * (float)s) * invn;
            float px = fmaf(dx, t, ox), py = fmaf(dy, t, oy), pz = fmaf(dz, t, oz);
            bool in = (!maskray) &&
                      !(px < -1.f || px > 1.f || py < -1.f || py > 1.f || pz < -1.f || pz > 1.f);
            float a = 0.f;
            if (in){
                int off[8]; float wc[8];
                tri_setup(px, py, pz, off, wc);
                float l0 = 0.f;
                #pragma unroll
                for (int k=0; k<8; k++) l0 = fmaf(wc[k], __ldg(dens + off[k]), l0);
                float xs = l0 + ACT_SHIFT;
                float sp = fmaxf(xs, 0.f) + log1pf(expf(-fabsf(xs)));
                a = 1.f - expf(-sp*0.5f);
                lmin = min(lmin, s); lmax = max(lmax, s);
            }
            aw[s] = a;
        }
        if (lmax >= 0){ atomicMin(&s_min, lmin); atomicMax(&s_max, lmax); }
        __syncthreads();

        // ---- parallel transmittance scan: 4 contiguous samples / thread ----
        int base4 = tid*4;
        float lp = 1.f;
        #pragma unroll
        for (int j=0; j<4; j++){
            int s = base4 + j;
            if (s < NS) lp *= fmaxf(1.f - aw[s], 1e-10f);
        }
        // inclusive scan within warp
        float v = lp;
        #pragma unroll
        for (int o=1; o<32; o<<=1){
            float n = __shfl_up_sync(0xffffffffu, v, o);
            if (lane >= o) v *= n;
        }
        if (lane == 31) s_wprod[wid] = v;
        __syncthreads();
        float warp_excl = 1.f;
        #pragma unroll
        for (int wj=0; wj<8; wj++)
            if (wj < wid) warp_excl *= s_wprod[wj];
        // exclusive within warp
        float vexcl = __shfl_up_sync(0xffffffffu, v, 1);
        if (lane == 0) vexcl = 1.f;
        float T = warp_excl * vexcl;

        int smn = s_min, smx = s_max;
        #pragma unroll
        for (int j=0; j<4; j++){
            int s = base4 + j;
            if (s < NS){
                float a = aw[s];
                if (s >= smn && s <= smx)
                    g_w[rid*NS + s] = a * T;
                T *= fmaxf(1.f - a, 1e-10f);
            }
        }

        if (tid == 0){
            float Tall = 1.f;
            #pragma unroll
            for (int wj=0; wj<8; wj++) Tall *= s_wprod[wj];
            g_T[rid]    = Tall;
            g_tmin[rid] = tmin;
            g_invn[rid] = invn;
            int cnt = (smx >= smn) ? (smx - smn + 1) : 0;
            g_sstart[rid] = (cnt > 0) ? smn : 0;
            g_scnt[rid]   = cnt;
        }
    }
}

// ---------------------------------------------------------------------------
// Kernel 2: shuffle-based exclusive scan + work reset.
// ---------------------------------------------------------------------------
__global__ void __launch_bounds__(1024) scan_kernel()
{
    __shared__ int wsum[32];
    int t = threadIdx.x;
    int lane = t & 31, wid = t >> 5;
    int v = g_scnt[t];
    #pragma unroll
    for (int o=1; o<32; o<<=1){
        int n = __shfl_up_sync(0xffffffffu, v, o);
        if (lane >= o) v += n;
    }
    if (lane == 31) wsum[wid] = v;
    __syncthreads();
    if (wid == 0){
        int w = wsum[lane];
        #pragma unroll
        for (int o=1; o<32; o<<=1){
            int n = __shfl_up_sync(0xffffffffu, w, o);
            if (lane >= o) w += n;
        }
        wsum[lane] = w;
    }
    __syncthreads();
    if (wid > 0) v += wsum[wid-1];
    g_base[t+1] = v;
    if (t == 0){ g_base[0] = 0; g_work = 0; }
    if (t == 1023) g_total = v;
}

// ---------------------------------------------------------------------------
// Kernel 3: pair-split MLP (unchanged from R6 win).
// ---------------------------------------------------------------------------
#define OFF_W0    0
#define OFF_W1    3464
#define OFF_W2    7568
#define OFF_W3    11672
#define OFF_B0    11864
#define OFF_B1    11928
#define OFF_B2    11992
#define OFF_B3    12056
#define OFF_BASE  12060
#define OFF_STAGE 13088
#define MLP_NTH   384
#define SH_FLOATS (OFF_STAGE + (MLP_NTH/2)*130)
#define SMEM_MLP  (SH_FLOATS*4)
#define MLP_BLOCKS 148

__device__ __forceinline__ void gemv_pair(u64* hA, u64* hB,
                                          const float* wbase,
                                          const float* fp, int R)
{
    for (int i=0; i<R; i++){
        float2 vp = *(const float2*)(fp + i*2);
        u64 vvA = f2pack(vp.x, vp.x);
        u64 vvB = f2pack(vp.y, vp.y);
        const ulonglong2* wr = (const ulonglong2*)(wbase + i*32);
        #pragma unroll
        for (int k=0; k<8; k++){
            ulonglong2 w2 = wr[k];
            hA[2*k]   = ffma2(vvA, w2.x, hA[2*k]);
            hA[2*k+1] = ffma2(vvA, w2.y, hA[2*k+1]);
            hB[2*k]   = ffma2(vvB, w2.x, hB[2*k]);
            hB[2*k+1] = ffma2(vvB, w2.y, hB[2*k+1]);
        }
    }
}

__device__ __forceinline__ void bias_init(u64* hA, u64* hB,
                                          const float* bias, int hf)
{
    const u64* bp = (const u64*)bias;
    #pragma unroll
    for (int k=0; k<16; k++){ u64 bb = bp[hf*16 + k]; hA[k]=bb; hB[k]=bb; }
}

__device__ __forceinline__ void relu_stage(const u64* hA, const u64* hB,
                                           float* fp, int hf)
{
    #pragma unroll
    for (int k=0; k<16; k++){
        float a0,a1,b0,b1;
        f2unpack(hA[k], a0, a1);
        f2unpack(hB[k], b0, b1);
        a0 = fmaxf(a0,0.f); a1 = fmaxf(a1,0.f);
        b0 = fmaxf(b0,0.f); b1 = fmaxf(b1,0.f);
        int n = hf*32 + 2*k;
        *(float2*)(fp + n*2)     = make_float2(a0, b0);
        *(float2*)(fp + n*2 + 2) = make_float2(a1, b1);
    }
}

__global__ void __launch_bounds__(MLP_NTH, 1) mlp_kernel(
    const float* __restrict__ ro,  const float* __restrict__ rdv,
    const float* __restrict__ vdv, const float* __restrict__ grid,
    const float* __restrict__ w0,  const float* __restrict__ b0,
    const float* __restrict__ w1,  const float* __restrict__ b1,
    const float* __restrict__ w2,  const float* __restrict__ b2,
    const float* __restrict__ w3,  const float* __restrict__ b3)
{
    extern __shared__ float sh[];
    int tid  = threadIdx.x;
    int lane = tid & 31;
    int hf   = tid & 1;
    int pg   = tid >> 1;
    int* sbase = (int*)(sh + OFF_BASE);

    for (int i=tid; i<54*64; i+=MLP_NTH){
        int r = i>>6, j = i&63;
        int dst = (j<32) ? (r*32+j) : (54*32+4 + r*32 + (j-32));
        sh[OFF_W0+dst] = w0[i];
    }
    for (int i=tid; i<64*64; i+=MLP_NTH){
        int r = i>>6, j = i&63;
        int dst = (j<32) ? (r*32+j) : (64*32+4 + r*32 + (j-32));
        sh[OFF_W1+dst] = w1[i];
        sh[OFF_W2+dst] = w2[i];
    }
    for (int i=tid; i<192; i+=MLP_NTH) sh[OFF_W3+i] = w3[i];
    for (int i=tid; i<64;  i+=MLP_NTH){
        sh[OFF_B0+i]=b0[i]; sh[OFF_B1+i]=b1[i]; sh[OFF_B2+i]=b2[i];
    }
    if (tid < 3) sh[OFF_B3+tid] = b3[tid];
    for (int i=tid; i<NRAYS+1; i+=MLP_NTH) sbase[i] = g_base[i];
    __syncthreads();

    int total   = g_total;
    int nchunks = (total + 31) >> 5;
    float* fp = sh + OFF_STAGE + pg*130;
    const float* wl0 = sh + OFF_W0 + hf*(54*32+4);
    const float* wl1 = sh + OFF_W1 + hf*(64*32+4);
    const float* wl2 = sh + OFF_W2 + hf*(64*32+4);

    while (true){
        int chunk = 0;
        if (lane == 0) chunk = atomicAdd(&g_work, 1);
        chunk = __shfl_sync(0xffffffffu, chunk, 0);
        if (chunk >= nchunks) break;
        int e = chunk*32 + lane;
        bool valid = (e < total);
        int ec = valid ? e : (total - 1);

        int lo = 0, hi = NRAYS;
        while (hi - lo > 1){
            int mid = (lo + hi) >> 1;
            if (sbase[mid] <= ec) lo = mid; else hi = mid;
        }
        int ray = lo;
        int s = g_sstart[ray] + (ec - sbase[ray]);

        float ox = __ldg(ro+ray*3+0), oy = __ldg(ro+ray*3+1), oz = __ldg(ro+ray*3+2);
        float dx = __ldg(rdv+ray*3+0), dy = __ldg(rdv+ray*3+1), dz = __ldg(rdv+ray*3+2);
        float vx = __ldg(vdv+ray*3+0), vy = __ldg(vdv+ray*3+1), vz = __ldg(vdv+ray*3+2);
        float tmin = __ldg(&g_tmin[ray]);
        float invn = __ldg(&g_invn[ray]);
        float wgt  = __ldg(&g_w[ray*NS + s]);

        float t  = tmin + (0.0078125f * (float)s) * invn;
        float px = fmaf(dx, t, ox), py = fmaf(dy, t, oy), pz = fmaf(dz, t, oz);

        int off[8]; float wc[8];
        tri_setup(px, py, pz, off, wc);

        float nvx[8], nvy[8], nvz[8];
        #pragma unroll
        for (int k=0; k<8; k++){
            nvx[k] = __ldg(g_norm + off[k]);
            nvy[k] = __ldg(g_norm + NVOX + off[k]);
            nvz[k] = __ldg(g_norm + 2*NVOX + off[k]);
        }

        for (int ch=1; ch<=15; ++ch){
            const float* gp = grid + ch*NVOX;
            float v = 0.f;
            #pragma unroll
            for (int k=0; k<8; k++) v = fmaf(wc[k], __ldg(gp + off[k]), v);
            fp[(ch-1)*2 + hf] = v;
        }

        float nsx = 0.f, nsy = 0.f, nsz = 0.f;
        #pragma unroll
        for (int k=0; k<8; k++){
            nsx = fmaf(wc[k], nvx[k], nsx);
            nsy = fmaf(wc[k], nvy[k], nsy);
            nsz = fmaf(wc[k], nvz[k], nsz);
        }
        float nl = sqrtf(nsx*nsx + nsy*nsy + nsz*nsz);
        float ninv = -1.f / fmaxf(nl, 1e-12f);
        nsx *= ninv; nsy *= ninv; nsz *= ninv;
        float dt  = -(vx*nsx + vy*nsy + vz*nsz);
        float rx = fmaf(2.f*dt, nsx, vx);
        float ry = fmaf(2.f*dt, nsy, vy);
        float rz = fmaf(2.f*dt, nsz, vz);
        fp[15*2 + hf] = rx;
        fp[16*2 + hf] = ry;
        fp[17*2 + hf] = rz;

        for (int f=0; f<6; ++f){
            float fr = (float)(1 << f);
            #pragma unroll
            for (int k3=0; k3<3; k3++){
                float ang = (k3==0 ? rx : (k3==1 ? ry : rz)) * fr;
                float kk = rintf(ang * 0.15915494309189535f);
                float r2 = fmaf(kk, -6.283185307179586f, ang);
                float sn, cs;
                sincosf(r2, &sn, &cs);
                fp[(18 + f*3 + k3)*2 + hf] = sn;
                fp[(36 + f*3 + k3)*2 + hf] = cs;
            }
        }
        __syncwarp();

        u64 hA[16], hB[16];
        bias_init(hA, hB, sh + OFF_B0, hf);
        gemv_pair(hA, hB, wl0, fp, 54);
        __syncwarp();
        relu_stage(hA, hB, fp, hf);
        __syncwarp();

        bias_init(hA, hB, sh + OFF_B1, hf);
        gemv_pair(hA, hB, wl1, fp, 64);
        __syncwarp();
        relu_stage(hA, hB, fp, hf);
        __syncwarp();

        bias_init(hA, hB, sh + OFF_B2, hf);
        gemv_pair(hA, hB, wl2, fp, 64);

        float pA0=0.f,pA1=0.f,pA2=0.f,pB0=0.f,pB1=0.f,pB2=0.f;
        #pragma unroll
        for (int k=0; k<16; k++){
            float a0,a1,b0v,b1v;
            f2unpack(hA[k], a0, a1);
            f2unpack(hB[k], b0v, b1v);
            a0 = fmaxf(a0,0.f); a1 = fmaxf(a1,0.f);
            b0v = fmaxf(b0v,0.f); b1v = fmaxf(b1v,0.f);
            int n0 = hf*32 + 2*k;
            float q00 = sh[OFF_W3 + n0*3 + 0];
            float q01 = sh[OFF_W3 + n0*3 + 1];
            float q02 = sh[OFF_W3 + n0*3 + 2];
            float q10 = sh[OFF_W3 + n0*3 + 3];
            float q11 = sh[OFF_W3 + n0*3 + 4];
            float q12 = sh[OFF_W3 + n0*3 + 5];
            pA0 = fmaf(a0,q00, fmaf(a1,q10, pA0));
            pA1 = fmaf(a0,q01, fmaf(a1,q11, pA1));
            pA2 = fmaf(a0,q02, fmaf(a1,q12, pA2));
            pB0 = fmaf(b0v,q00, fmaf(b1v,q10, pB0));
            pB1 = fmaf(b0v,q01, fmaf(b1v,q11, pB1));
            pB2 = fmaf(b0v,q02, fmaf(b1v,q12, pB2));
        }
        pA0 += __shfl_xor_sync(0xffffffffu, pA0, 1);
        pA1 += __shfl_xor_sync(0xffffffffu, pA1, 1);
        pA2 += __shfl_xor_sync(0xffffffffu, pA2, 1);
        pB0 += __shfl_xor_sync(0xffffffffu, pB0, 1);
        pB1 += __shfl_xor_sync(0xffffffffu, pB1, 1);
        pB2 += __shfl_xor_sync(0xffffffffu, pB2, 1);

        float c0s = (hf ? pB0 : pA0) + sh[OFF_B3+0];
        float c1s = (hf ? pB1 : pA1) + sh[OFF_B3+1];
        float c2s = (hf ? pB2 : pA2) + sh[OFF_B3+2];
        float col0 = 1.f / (1.f + expf(-c0s));
        float col1 = 1.f / (1.f + expf(-c1s));
        float col2 = 1.f / (1.f + expf(-c2s));
        if (valid){
            g_c0[e] = wgt * col0;
            g_c1[e] = wgt * col1;
            g_c2[e] = wgt * col2;
        }
    }
}

// ---------------------------------------------------------------------------
// Kernel 4: per-ray deterministic reduction + background.
// ---------------------------------------------------------------------------
__global__ void __launch_bounds__(32) reduce_kernel(float* __restrict__ out)
{
    int ray = blockIdx.x;
    int lane = threadIdx.x;
    int base = g_base[ray];
    int cnt  = g_base[ray+1] - base;
    float a0 = 0.f, a1 = 0.f, a2 = 0.f;
    for (int i=lane; i<cnt; i+=32){
        a0 += g_c0[base+i];
        a1 += g_c1[base+i];
        a2 += g_c2[base+i];
    }
    #pragma unroll
    for (int o=16; o; o>>=1){
        a0 += __shfl_down_sync(0xffffffffu, a0, o);
        a1 += __shfl_down_sync(0xffffffffu, a1, o);
        a2 += __shfl_down_sync(0xffffffffu, a2, o);
    }
    if (lane == 0){
        float Tf = g_T[ray];
        out[ray*3+0] = a0 + Tf;
        out[ray*3+1] = a1 + Tf;
        out[ray*3+2] = a2 + Tf;
    }
}

extern "C" void kernel_launch(void* const* d_in, const int* in_sizes, int n_in,
                              void* d_out, int out_size)
{
    (void)in_sizes; (void)n_in; (void)out_size;
    const float* ro    = (const float*)d_in[0];
    const float* rd    = (const float*)d_in[1];
    const float* vd    = (const float*)d_in[2];
    const float* grid  = (const float*)d_in[3];
    const float* sobel = (const float*)d_in[4];
    const float* w0 = (const float*)d_in[5];
    const float* b0 = (const float*)d_in[6];
    const float* w1 = (const float*)d_in[7];
    const float* b1 = (const float*)d_in[8];
    const float* w2 = (const float*)d_in[9];
    const float* b2 = (const float*)d_in[10];
    const float* w3 = (const float*)d_in[11];
    const float* b3 = (const float*)d_in[12];
    float* out = (float*)d_out;

    fused_kernel<<<CONV_BLOCKS + NRAYS, 256>>>(grid, sobel, ro, rd);
    scan_kernel<<<1, 1024>>>();

    static int smem_set = 0;
    if (!smem_set){
        cudaFuncSetAttribute(mlp_kernel,
                             cudaFuncAttributeMaxDynamicSharedMemorySize, SMEM_MLP);
        smem_set = 1;
    }
    mlp_kernel<<<MLP_BLOCKS, MLP_NTH, SMEM_MLP>>>(ro, rd, vd, grid,
                                                  w0, b0, w1, b1, w2, b2, w3, b3);
    reduce_kernel<<<NRAYS, 32>>>(out);
}